// round 14
// baseline (speedup 1.0000x reference)
#include <cuda_runtime.h>
#include <cuda_bf16.h>
#include <math.h>

#define NN 30000
#define EE 480000
#define D_IN 128
#define D_HID 256
#define EPS 1e-5f

// ---------------- scratch (device globals; no allocation) ----------------
__device__ float g_m1 [NN * D_IN];
__device__ float g_agg1[NN * D_IN];
__device__ float g_h1 [NN * D_HID];
__device__ float g_cls[NN * 5];
__device__ float g_P  [NN * D_HID];
__device__ float g_Q  [NN * D_HID];
__device__ float g_m2 [NN * D_HID];
__device__ float g_agg2[NN * D_HID];
__device__ int g_deg [NN];
__device__ int g_cur [NN];
__device__ int g_rowstart[NN + 1];
__device__ int g_csrc[EE];
__device__ int g_cdst[EE];
__device__ int g_eid [EE];

// ---------------- CSR build ----------------
__global__ void csr_zero_k() {
    int i = blockIdx.x * blockDim.x + threadIdx.x;
    if (i < NN) { g_deg[i] = 0; g_cur[i] = 0; }
}
__global__ void csr_hist_k(const int* __restrict__ dst) {
    int e = blockIdx.x * blockDim.x + threadIdx.x;
    if (e < EE) atomicAdd(&g_deg[dst[e]], 1);
}
__global__ void csr_scan_k() {
    __shared__ int s[1024];
    int t = threadIdx.x;
    const int C = (NN + 1023) / 1024;
    int base = t * C;
    int sum = 0;
    for (int i = 0; i < C; i++) { int idx = base + i; if (idx < NN) sum += g_deg[idx]; }
    s[t] = sum; __syncthreads();
    for (int off = 1; off < 1024; off <<= 1) {
        int v = (t >= off) ? s[t - off] : 0;
        __syncthreads();
        s[t] += v;
        __syncthreads();
    }
    int run = (t > 0) ? s[t - 1] : 0;
    for (int i = 0; i < C; i++) {
        int idx = base + i;
        if (idx < NN) { g_rowstart[idx] = run; run += g_deg[idx]; }
    }
    if (t == 1023) g_rowstart[NN] = EE;
}
__global__ void csr_fill_k(const int* __restrict__ src, const int* __restrict__ dst) {
    int e = blockIdx.x * blockDim.x + threadIdx.x;
    if (e >= EE) return;
    int d = dst[e];
    int pos = g_rowstart[d] + atomicAdd(&g_cur[d], 1);
    g_csrc[pos] = src[e];
    g_cdst[pos] = d;
    g_eid[pos]  = e;
}

// ---------------- gather segment-max ----------------
__global__ void gather_max_128(const float* __restrict__ msg, float* __restrict__ agg) {
    int warp = (blockIdx.x * blockDim.x + threadIdx.x) >> 5;
    int lane = threadIdx.x & 31;
    if (warp >= NN) return;
    int rs = g_rowstart[warp], re = g_rowstart[warp + 1];
    float4 v = make_float4(0.f, 0.f, 0.f, 0.f);
    for (int j = rs; j < re; j++) {
        int s = g_csrc[j];
        float4 m = *(const float4*)(msg + (size_t)s * 128 + lane * 4);
        v.x = fmaxf(v.x, m.x); v.y = fmaxf(v.y, m.y);
        v.z = fmaxf(v.z, m.z); v.w = fmaxf(v.w, m.w);
    }
    *(float4*)(agg + (size_t)warp * 128 + lane * 4) = v;
}
__global__ void gather_max_256(const float* __restrict__ msg, float* __restrict__ agg) {
    int warp = (blockIdx.x * blockDim.x + threadIdx.x) >> 5;
    int lane = threadIdx.x & 31;
    if (warp >= NN) return;
    int rs = g_rowstart[warp], re = g_rowstart[warp + 1];
    float4 v0 = make_float4(0.f, 0.f, 0.f, 0.f);
    float4 v1 = v0;
    for (int j = rs; j < re; j++) {
        int s = g_csrc[j];
        const float* row = msg + (size_t)s * 256;
        float4 a = *(const float4*)(row + lane * 4);
        float4 b = *(const float4*)(row + 128 + lane * 4);
        v0.x = fmaxf(v0.x, a.x); v0.y = fmaxf(v0.y, a.y);
        v0.z = fmaxf(v0.z, a.z); v0.w = fmaxf(v0.w, a.w);
        v1.x = fmaxf(v1.x, b.x); v1.y = fmaxf(v1.y, b.y);
        v1.z = fmaxf(v1.z, b.z); v1.w = fmaxf(v1.w, b.w);
    }
    *(float4*)(agg + (size_t)warp * 256 + lane * 4) = v0;
    *(float4*)(agg + (size_t)warp * 256 + 128 + lane * 4) = v1;
}

// ---------------- tf32 GEMM: persistent, tile 128x64, 3 CTAs/SM ----------
__device__ __forceinline__ unsigned f2tf32(float v) {
    unsigned r;
    asm("cvt.rna.tf32.f32 %0, %1;" : "=r"(r) : "f"(v));
    return r;
}
__device__ __forceinline__ void mma_tf32(float& c0, float& c1, float& c2, float& c3,
                                         unsigned a0, unsigned a1, unsigned a2, unsigned a3,
                                         unsigned b0, unsigned b1) {
    asm volatile("mma.sync.aligned.m16n8k8.row.col.f32.tf32.tf32.f32 "
                 "{%0,%1,%2,%3}, {%4,%5,%6,%7}, {%8,%9}, {%0,%1,%2,%3};"
                 : "+f"(c0), "+f"(c1), "+f"(c2), "+f"(c3)
                 : "r"(a0), "r"(a1), "r"(a2), "r"(a3), "r"(b0), "r"(b1));
}

#define AS_STRIDE 36                 // proven conflict-free A pattern
#define BS_STRIDE 72                 // 72 % 32 == 8 -> preserves 8q+g bank walk
#define AS_ELEMS (128 * AS_STRIDE)
#define BS_ELEMS (32 * BS_STRIDE)
#define TG_SMEM ((AS_ELEMS + BS_ELEMS) * 4)   // 27648 B -> 3 CTAs/SM

template<bool HAS2, bool BIAS, bool RELU, bool DUAL>
__global__ __launch_bounds__(256, 3) void tgemm(
        const float* __restrict__ A, const float* __restrict__ W,
        const float* __restrict__ A2, const float* __restrict__ W2,
        const float* __restrict__ bias, float* __restrict__ out,
        const float* __restrict__ Wb, float* __restrict__ outb,
        const float* __restrict__ cls5, const float* __restrict__ Wp5,
        const float* __restrict__ Wq5, const float* __restrict__ b1f,
        int M, int K, int N) {
    extern __shared__ unsigned sm[];
    unsigned* As = sm;                 // [128][36]
    unsigned* Bs = sm + AS_ELEMS;      // [32][72]
    int t = threadIdx.x;
    int w = t >> 5, lane = t & 31;
    int g = lane >> 2, q = lane & 3;
    int wm = (w >> 1) * 32, wn = (w & 1) * 32;   // 4x2 warp grid, 32x32 warp tiles
    int a_row = t >> 3, a_k = (t & 7) * 4;       // A loads: 4 phases of 32 rows
    int b_k = t >> 4, b_n = (t & 15) * 4;        // B loads: 2 phases of 16 k-rows

    int mtiles = (M + 127) >> 7;
    int ntiles = N >> 6;
    int tot = mtiles * ntiles;
    int tot_all = DUAL ? tot * 2 : tot;
    int kslabs = K >> 5;
    int nslab = (HAS2 ? 2 : 1) * kslabs;

    for (int tt = blockIdx.x; tt < tot_all; tt += gridDim.x) {
        bool second = DUAL && (tt >= tot);
        int tile = second ? tt - tot : tt;
        const float* Wsel = second ? Wb : W;
        float* outsel = second ? outb : out;
        int bm = (tile / ntiles) * 128, bn = (tile % ntiles) * 64;

        float acc[2][4][4];
        #pragma unroll
        for (int i = 0; i < 2; i++)
            #pragma unroll
            for (int j = 0; j < 4; j++)
                #pragma unroll
                for (int r = 0; r < 4; r++) acc[i][j][r] = 0.f;

        for (int j = 0; j < nslab; j++) {
            const float* Ap = (HAS2 && j >= kslabs) ? A2 : A;
            const float* Wp = (HAS2 && j >= kslabs) ? W2 : Wsel;
            int k0 = (j & (kslabs - 1)) << 5;
            float4 aP[4], wP[2];
            #pragma unroll
            for (int ph = 0; ph < 4; ph++) {
                int grow = bm + a_row + ph * 32;
                aP[ph] = make_float4(0.f, 0.f, 0.f, 0.f);
                if (grow < M) aP[ph] = *(const float4*)(Ap + (size_t)grow * K + k0 + a_k);
            }
            #pragma unroll
            for (int ph = 0; ph < 2; ph++)
                wP[ph] = *(const float4*)(Wp + (size_t)(k0 + b_k + ph * 16) * N + bn + b_n);
            __syncthreads();   // previous slab's compute (or prior tile epilogue) done
            #pragma unroll
            for (int ph = 0; ph < 4; ph++) {
                unsigned* p = &As[(a_row + ph * 32) * AS_STRIDE + a_k];
                p[0] = f2tf32(aP[ph].x); p[1] = f2tf32(aP[ph].y);
                p[2] = f2tf32(aP[ph].z); p[3] = f2tf32(aP[ph].w);
            }
            #pragma unroll
            for (int ph = 0; ph < 2; ph++) {
                unsigned* pw = &Bs[(b_k + ph * 16) * BS_STRIDE + b_n];
                pw[0] = f2tf32(wP[ph].x); pw[1] = f2tf32(wP[ph].y);
                pw[2] = f2tf32(wP[ph].z); pw[3] = f2tf32(wP[ph].w);
            }
            __syncthreads();
            #pragma unroll
            for (int kk = 0; kk < 32; kk += 8) {
                unsigned af[2][4], bf[4][2];
                #pragma unroll
                for (int mi = 0; mi < 2; mi++) {
                    const unsigned* p = &As[(wm + mi * 16 + g) * AS_STRIDE + kk + q];
                    af[mi][0] = p[0];
                    af[mi][1] = p[8 * AS_STRIDE];
                    af[mi][2] = p[4];
                    af[mi][3] = p[8 * AS_STRIDE + 4];
                }
                #pragma unroll
                for (int ni = 0; ni < 4; ni++) {
                    const unsigned* p = &Bs[(kk + q) * BS_STRIDE + wn + ni * 8 + g];
                    bf[ni][0] = p[0];
                    bf[ni][1] = p[4 * BS_STRIDE];
                }
                #pragma unroll
                for (int mi = 0; mi < 2; mi++)
                    #pragma unroll
                    for (int ni = 0; ni < 4; ni++)
                        mma_tf32(acc[mi][ni][0], acc[mi][ni][1], acc[mi][ni][2], acc[mi][ni][3],
                                 af[mi][0], af[mi][1], af[mi][2], af[mi][3],
                                 bf[ni][0], bf[ni][1]);
            }
        }

        // DUAL: stage rank-5 fold weights (+ b1 for Q) into smem (reuse As region)
        float* fw = (float*)sm;        // [5][64]
        float* fb = fw + 5 * 64;       // [64]
        if (DUAL) {
            __syncthreads();           // all warps done reading As/Bs
            const float* Wf = second ? Wq5 : Wp5;
            for (int i = t; i < 5 * 64; i += 256) {
                int r = i >> 6, c = i & 63;
                fw[i] = Wf[r * 256 + bn + c];
            }
            if (second) for (int i = t; i < 64; i += 256) fb[i] = b1f[bn + i];
            __syncthreads();
        }

        #pragma unroll
        for (int mi = 0; mi < 2; mi++) {
            int r0 = bm + wm + mi * 16 + g;
            float cA[5], cB[5];
            if (DUAL) {
                #pragma unroll
                for (int i = 0; i < 5; i++) {
                    cA[i] = (r0 < M) ? cls5[(size_t)r0 * 5 + i] : 0.f;
                    cB[i] = (r0 + 8 < M) ? cls5[(size_t)(r0 + 8) * 5 + i] : 0.f;
                }
            }
            #pragma unroll
            for (int ni = 0; ni < 4; ni++) {
                int colL = wn + ni * 8 + q * 2;
                int col = bn + colL;
                float b0 = 0.f, b1v = 0.f;
                if (BIAS) { b0 = bias[col]; b1v = bias[col + 1]; }
                float2 lo, hi;
                lo.x = acc[mi][ni][0] + b0; lo.y = acc[mi][ni][1] + b1v;
                hi.x = acc[mi][ni][2] + b0; hi.y = acc[mi][ni][3] + b1v;
                if (DUAL) {
                    float d0a = 0.f, d1a = 0.f, d0b = 0.f, d1b = 0.f;
                    #pragma unroll
                    for (int i = 0; i < 5; i++) {
                        float w0 = fw[i * 64 + colL], w1 = fw[i * 64 + colL + 1];
                        d0a += cA[i] * w0; d1a += cA[i] * w1;
                        d0b += cB[i] * w0; d1b += cB[i] * w1;
                    }
                    lo.x += d0a; lo.y += d1a;
                    hi.x += d0b; hi.y += d1b;
                    if (second) {
                        float fb0 = fb[colL], fb1 = fb[colL + 1];
                        lo.x += fb0; lo.y += fb1;
                        hi.x += fb0; hi.y += fb1;
                    }
                }
                if (RELU) {
                    lo.x = fmaxf(lo.x, 0.f); lo.y = fmaxf(lo.y, 0.f);
                    hi.x = fmaxf(hi.x, 0.f); hi.y = fmaxf(hi.y, 0.f);
                }
                if (r0 < M)     *(float2*)(outsel + (size_t)r0 * N + col) = lo;
                if (r0 + 8 < M) *(float2*)(outsel + (size_t)(r0 + 8) * N + col) = hi;
            }
        }
    }
}

// ---------------- node head ----------------
__global__ void node_head_k(const float* __restrict__ h1, const float* __restrict__ npW,
                            const float* __restrict__ npb, const float* __restrict__ g,
                            const float* __restrict__ beta, float* __restrict__ node_pred,
                            float* __restrict__ cls) {
    int warp = (blockIdx.x * blockDim.x + threadIdx.x) >> 5;
    int lane = threadIdx.x & 31;
    if (warp >= NN) return;
    const float* row = h1 + (size_t)warp * D_HID;
    float p[5] = {};
    for (int k = lane; k < D_HID; k += 32) {
        float hv = row[k];
        #pragma unroll
        for (int j = 0; j < 5; j++) p[j] += hv * npW[k * 5 + j];
    }
    #pragma unroll
    for (int off = 16; off; off >>= 1)
        #pragma unroll
        for (int j = 0; j < 5; j++) p[j] += __shfl_xor_sync(0xffffffffu, p[j], off);
    #pragma unroll
    for (int j = 0; j < 5; j++) p[j] += npb[j];
    float mu = (p[0] + p[1] + p[2] + p[3] + p[4]) * 0.2f;
    float var = 0.f;
    #pragma unroll
    for (int j = 0; j < 5; j++) { float t = p[j] - mu; var += t * t; }
    var *= 0.2f;
    float inv = rsqrtf(var + EPS);
    float y[5];
    #pragma unroll
    for (int j = 0; j < 5; j++) y[j] = g[j] * (p[j] - mu) * inv + beta[j];
    float mx = y[0];
    #pragma unroll
    for (int j = 1; j < 5; j++) mx = fmaxf(mx, y[j]);
    float es[5], se = 0.f;
    #pragma unroll
    for (int j = 0; j < 5; j++) { es[j] = __expf(y[j] - mx); se += es[j]; }
    float rse = 1.f / se;
    if (lane == 0) {
        #pragma unroll
        for (int j = 0; j < 5; j++) {
            node_pred[(size_t)warp * 5 + j] = y[j];
            cls[(size_t)warp * 5 + j] = es[j] * rse;
        }
    }
}

// ---------------- edge head: reg weights + cached Q row (CSR dst-grouped) ----------
#define EH_EPW 16
__global__ __launch_bounds__(256, 2) void edge_head_k(
        const float* __restrict__ P, const float* __restrict__ Q,
        const float* __restrict__ efeat, const float* __restrict__ W1,
        const float* __restrict__ g, const float* __restrict__ beta,
        const float* __restrict__ W2, const float* __restrict__ b2,
        float* __restrict__ out) {
    int gw = (blockIdx.x * blockDim.x + threadIdx.x) >> 5;
    int lane = threadIdx.x & 31;
    int f0 = lane * 8;

    float we[6][8];
    #pragma unroll
    for (int i = 0; i < 6; i++) {
        float4 a = *(const float4*)(W1 + (261 + i) * 256 + f0);
        float4 b = *(const float4*)(W1 + (261 + i) * 256 + f0 + 4);
        we[i][0] = a.x; we[i][1] = a.y; we[i][2] = a.z; we[i][3] = a.w;
        we[i][4] = b.x; we[i][5] = b.y; we[i][6] = b.z; we[i][7] = b.w;
    }
    float w2a[8], w2b[8], gv[8], bv[8];
    #pragma unroll
    for (int i = 0; i < 8; i++) {
        w2a[i] = W2[(f0 + i) * 2 + 0];
        w2b[i] = W2[(f0 + i) * 2 + 1];
        gv[i] = g[f0 + i];
        bv[i] = beta[f0 + i];
    }
    float b20 = b2[0], b21 = b2[1];

    int jbase = gw * EH_EPW;
    int d_prev = -1;
    float qc[8];
    #pragma unroll 1
    for (int ii = 0; ii < EH_EPW; ii++) {
        int j = jbase + ii;
        if (j >= EE) break;
        int s = g_csrc[j], d = g_cdst[j], e = g_eid[j];
        if (d != d_prev) {
            float4 qa = *(const float4*)(Q + (size_t)d * 256 + f0);
            float4 qb = *(const float4*)(Q + (size_t)d * 256 + f0 + 4);
            qc[0] = qa.x; qc[1] = qa.y; qc[2] = qa.z; qc[3] = qa.w;
            qc[4] = qb.x; qc[5] = qb.y; qc[6] = qb.z; qc[7] = qb.w;
            d_prev = d;
        }
        float y[8];
        {
            float4 pa = *(const float4*)(P + (size_t)s * 256 + f0);
            float4 pb = *(const float4*)(P + (size_t)s * 256 + f0 + 4);
            y[0] = pa.x + qc[0]; y[1] = pa.y + qc[1]; y[2] = pa.z + qc[2]; y[3] = pa.w + qc[3];
            y[4] = pb.x + qc[4]; y[5] = pb.y + qc[5]; y[6] = pb.z + qc[6]; y[7] = pb.w + qc[7];
        }
        float ev = 0.f;
        if (lane < 6) ev = efeat[(size_t)e * 6 + lane];
        #pragma unroll
        for (int i = 0; i < 6; i++) {
            float ci = __shfl_sync(0xffffffffu, ev, i);
            #pragma unroll
            for (int r = 0; r < 8; r++) y[r] += ci * we[i][r];
        }
        float sum = 0.f;
        #pragma unroll
        for (int i = 0; i < 8; i++) sum += y[i];
        #pragma unroll
        for (int off = 16; off; off >>= 1) sum += __shfl_xor_sync(0xffffffffu, sum, off);
        float mu = sum * (1.f / 256.f);
        float vs = 0.f;
        #pragma unroll
        for (int i = 0; i < 8; i++) { float t = y[i] - mu; vs += t * t; }
        #pragma unroll
        for (int off = 16; off; off >>= 1) vs += __shfl_xor_sync(0xffffffffu, vs, off);
        float inv = rsqrtf(vs * (1.f / 256.f) + EPS);
        float o0 = 0.f, o1 = 0.f;
        #pragma unroll
        for (int i = 0; i < 8; i++) {
            float yn = gv[i] * (y[i] - mu) * inv + bv[i];
            yn = fmaxf(yn, 0.f);
            o0 += yn * w2a[i];
            o1 += yn * w2b[i];
        }
        #pragma unroll
        for (int off = 16; off; off >>= 1) {
            o0 += __shfl_xor_sync(0xffffffffu, o0, off);
            o1 += __shfl_xor_sync(0xffffffffu, o1, off);
        }
        if (lane == 0) {
            out[(size_t)e * 2 + 0] = o0 + b20;
            out[(size_t)e * 2 + 1] = o1 + b21;
        }
    }
}

// ---------------- launch ----------------
static inline int ggrid(int tiles) {
    const int cap = 444;   // 148 SMs x 3 CTAs/SM
    int passes = (tiles + cap - 1) / cap;
    return (tiles + passes - 1) / passes;
}

extern "C" void kernel_launch(void* const* d_in, const int* in_sizes, int n_in,
                              void* d_out, int out_size) {
    const float* h        = (const float*)d_in[0];
    const float* efeat    = (const float*)d_in[1];
    const int*   src      = (const int*)  d_in[2];
    const int*   dst      = (const int*)  d_in[3];
    const float* encWpool = (const float*)d_in[4];
    const float* encbpool = (const float*)d_in[5];
    const float* encWself = (const float*)d_in[6];
    const float* encbself = (const float*)d_in[7];
    const float* encWneigh= (const float*)d_in[8];
    const float* npW      = (const float*)d_in[9];
    const float* npb      = (const float*)d_in[10];
    const float* npg      = (const float*)d_in[11];
    const float* npbeta   = (const float*)d_in[12];
    const float* epW1     = (const float*)d_in[13];
    const float* epb1     = (const float*)d_in[14];
    const float* epg      = (const float*)d_in[15];
    const float* epbeta   = (const float*)d_in[16];
    const float* epW2     = (const float*)d_in[17];
    const float* epb2     = (const float*)d_in[18];
    const float* decWpool = (const float*)d_in[19];
    const float* decbpool = (const float*)d_in[20];
    const float* decWself = (const float*)d_in[21];
    const float* decbself = (const float*)d_in[22];
    const float* decWneigh= (const float*)d_in[23];

    float* out       = (float*)d_out;
    float* node_pred = out;
    float* edge_pred = out + NN * 5;
    float* h2        = out + NN * 5 + EE * 2;

    float *m1, *agg1, *h1, *cls, *P, *Q, *m2, *agg2;
    cudaGetSymbolAddress((void**)&m1,  g_m1);
    cudaGetSymbolAddress((void**)&agg1,g_agg1);
    cudaGetSymbolAddress((void**)&h1,  g_h1);
    cudaGetSymbolAddress((void**)&cls, g_cls);
    cudaGetSymbolAddress((void**)&P,   g_P);
    cudaGetSymbolAddress((void**)&Q,   g_Q);
    cudaGetSymbolAddress((void**)&m2,  g_m2);
    cudaGetSymbolAddress((void**)&agg2,g_agg2);

    static cudaStream_t s2 = nullptr;
    static cudaEvent_t evFork1 = nullptr, evJoin1 = nullptr, evFork2 = nullptr,
                       evJoin2 = nullptr;
    if (s2 == nullptr) {
        cudaStreamCreateWithFlags(&s2, cudaStreamNonBlocking);
        cudaEventCreateWithFlags(&evFork1, cudaEventDisableTiming);
        cudaEventCreateWithFlags(&evJoin1, cudaEventDisableTiming);
        cudaEventCreateWithFlags(&evFork2, cudaEventDisableTiming);
        cudaEventCreateWithFlags(&evJoin2, cudaEventDisableTiming);
        cudaFuncSetAttribute(tgemm<false, true,  true,  false>, cudaFuncAttributeMaxDynamicSharedMemorySize, TG_SMEM);
        cudaFuncSetAttribute(tgemm<true,  true,  true,  false>, cudaFuncAttributeMaxDynamicSharedMemorySize, TG_SMEM);
        cudaFuncSetAttribute(tgemm<false, false, false, true >, cudaFuncAttributeMaxDynamicSharedMemorySize, TG_SMEM);
    }

    // launches 0-2: CSR prefix (main stream)
    csr_zero_k<<<(NN + 255) / 256, 256>>>();
    csr_hist_k<<<(EE + 255) / 256, 256>>>(dst);
    csr_scan_k<<<1, 1024>>>();

    // fork 1: csr_fill on s2, concurrent with enc-pool GEMM on main
    cudaEventRecord(evFork1, 0);
    cudaStreamWaitEvent(s2, evFork1, 0);

    // launch 3 (profiled slot): encoder pool GEMM (main); N=128 -> 2 ntiles -> 470 tiles
    tgemm<false, true, true, false><<<ggrid(470), 256, TG_SMEM>>>(
        h, encWpool, nullptr, nullptr, encbpool, m1, nullptr, nullptr,
        nullptr, nullptr, nullptr, nullptr, NN, D_IN, D_IN);

    csr_fill_k<<<(EE + 255) / 256, 256, 0, s2>>>(src, dst);
    cudaEventRecord(evJoin1, s2);
    cudaStreamWaitEvent(0, evJoin1, 0);

    gather_max_128<<<(NN * 32 + 255) / 256, 256>>>(m1, agg1);

    tgemm<true, true, true, false><<<ggrid(940), 256, TG_SMEM>>>(
        h, encWself, agg1, encWneigh, encbself, h1, nullptr, nullptr,
        nullptr, nullptr, nullptr, nullptr, NN, D_IN, D_HID);

    // node head on main (cls must precede the fused P/Q GEMM)
    node_head_k<<<(NN * 32 + 255) / 256, 256>>>(h1, npW, npb, npg, npbeta, node_pred, cls);

    // fork 2: decoder branch on s2, edge branch on main
    cudaEventRecord(evFork2, 0);
    cudaStreamWaitEvent(s2, evFork2, 0);

    tgemm<false, true, true, false><<<ggrid(940), 256, TG_SMEM, s2>>>(
        h1, decWpool, nullptr, nullptr, decbpool, m2, nullptr, nullptr,
        nullptr, nullptr, nullptr, nullptr, NN, D_HID, D_HID);
    gather_max_256<<<(NN * 32 + 255) / 256, 256, 0, s2>>>(m2, agg2);
    tgemm<true, true, true, false><<<ggrid(470), 256, TG_SMEM, s2>>>(
        h1, decWself, agg2, decWneigh, decbself, h2, nullptr, nullptr,
        nullptr, nullptr, nullptr, nullptr, NN, D_HID, D_IN);
    cudaEventRecord(evJoin2, s2);

    // edge branch (main): fused P/Q GEMM (fold inlined) -> edge head
    tgemm<false, false, false, true><<<ggrid(1880), 256, TG_SMEM>>>(
        h1, epW1, nullptr, nullptr, nullptr, P, epW1 + 267 * 256, Q,
        cls, epW1 + 256 * 256, epW1 + 523 * 256, epb1, NN, D_HID, D_HID);
    edge_head_k<<<(EE + EH_EPW * 8 - 1) / (EH_EPW * 8), 256>>>(
        P, Q, efeat, epW1, epg, epbeta, epW2, epb2, edge_pred);

    // join decoder branch back into main
    cudaStreamWaitEvent(0, evJoin2, 0);
}

// round 15
// speedup vs baseline: 1.0908x; 1.0908x over previous
#include <cuda_runtime.h>
#include <cuda_bf16.h>
#include <math.h>

#define NN 30000
#define EE 480000
#define D_IN 128
#define D_HID 256
#define EPS 1e-5f

// ---------------- scratch (device globals; no allocation) ----------------
__device__ float g_m1 [NN * D_IN];
__device__ float g_agg1[NN * D_IN];
__device__ float g_h1 [NN * D_HID];
__device__ float g_cls[NN * 5];
__device__ float g_P  [NN * D_HID];
__device__ float g_Q  [NN * D_HID];
__device__ float g_m2 [NN * D_HID];
__device__ float g_agg2[NN * D_HID];
__device__ int g_deg [NN];
__device__ int g_cur [NN];
__device__ int g_rowstart[NN + 1];
__device__ int g_csrc[EE];
__device__ int g_cdst[EE];
__device__ int g_eid [EE];

// ---------------- CSR build ----------------
__global__ void csr_zero_k() {
    int i = blockIdx.x * blockDim.x + threadIdx.x;
    if (i < NN) { g_deg[i] = 0; g_cur[i] = 0; }
}
__global__ void csr_hist_k(const int* __restrict__ dst) {
    int e = blockIdx.x * blockDim.x + threadIdx.x;
    if (e < EE) atomicAdd(&g_deg[dst[e]], 1);
}
__global__ void csr_scan_k() {
    __shared__ int s[1024];
    int t = threadIdx.x;
    const int C = (NN + 1023) / 1024;
    int base = t * C;
    int sum = 0;
    for (int i = 0; i < C; i++) { int idx = base + i; if (idx < NN) sum += g_deg[idx]; }
    s[t] = sum; __syncthreads();
    for (int off = 1; off < 1024; off <<= 1) {
        int v = (t >= off) ? s[t - off] : 0;
        __syncthreads();
        s[t] += v;
        __syncthreads();
    }
    int run = (t > 0) ? s[t - 1] : 0;
    for (int i = 0; i < C; i++) {
        int idx = base + i;
        if (idx < NN) { g_rowstart[idx] = run; run += g_deg[idx]; }
    }
    if (t == 1023) g_rowstart[NN] = EE;
}
__global__ void csr_fill_k(const int* __restrict__ src, const int* __restrict__ dst) {
    int e = blockIdx.x * blockDim.x + threadIdx.x;
    if (e >= EE) return;
    int d = dst[e];
    int pos = g_rowstart[d] + atomicAdd(&g_cur[d], 1);
    g_csrc[pos] = src[e];
    g_cdst[pos] = d;
    g_eid[pos]  = e;
}

// ---------------- gather segment-max ----------------
__global__ void gather_max_128(const float* __restrict__ msg, float* __restrict__ agg) {
    int warp = (blockIdx.x * blockDim.x + threadIdx.x) >> 5;
    int lane = threadIdx.x & 31;
    if (warp >= NN) return;
    int rs = g_rowstart[warp], re = g_rowstart[warp + 1];
    float4 v = make_float4(0.f, 0.f, 0.f, 0.f);
    for (int j = rs; j < re; j++) {
        int s = g_csrc[j];
        float4 m = *(const float4*)(msg + (size_t)s * 128 + lane * 4);
        v.x = fmaxf(v.x, m.x); v.y = fmaxf(v.y, m.y);
        v.z = fmaxf(v.z, m.z); v.w = fmaxf(v.w, m.w);
    }
    *(float4*)(agg + (size_t)warp * 128 + lane * 4) = v;
}
__global__ void gather_max_256(const float* __restrict__ msg, float* __restrict__ agg) {
    int warp = (blockIdx.x * blockDim.x + threadIdx.x) >> 5;
    int lane = threadIdx.x & 31;
    if (warp >= NN) return;
    int rs = g_rowstart[warp], re = g_rowstart[warp + 1];
    float4 v0 = make_float4(0.f, 0.f, 0.f, 0.f);
    float4 v1 = v0;
    for (int j = rs; j < re; j++) {
        int s = g_csrc[j];
        const float* row = msg + (size_t)s * 256;
        float4 a = *(const float4*)(row + lane * 4);
        float4 b = *(const float4*)(row + 128 + lane * 4);
        v0.x = fmaxf(v0.x, a.x); v0.y = fmaxf(v0.y, a.y);
        v0.z = fmaxf(v0.z, a.z); v0.w = fmaxf(v0.w, a.w);
        v1.x = fmaxf(v1.x, b.x); v1.y = fmaxf(v1.y, b.y);
        v1.z = fmaxf(v1.z, b.z); v1.w = fmaxf(v1.w, b.w);
    }
    *(float4*)(agg + (size_t)warp * 256 + lane * 4) = v0;
    *(float4*)(agg + (size_t)warp * 256 + 128 + lane * 4) = v1;
}

// ---------------- tf32 GEMM: persistent + 2-stage (R9/R13-proven, FROZEN) ----------
__device__ __forceinline__ unsigned f2tf32(float v) {
    unsigned r;
    asm("cvt.rna.tf32.f32 %0, %1;" : "=r"(r) : "f"(v));
    return r;
}
__device__ __forceinline__ void mma_tf32(float& c0, float& c1, float& c2, float& c3,
                                         unsigned a0, unsigned a1, unsigned a2, unsigned a3,
                                         unsigned b0, unsigned b1) {
    asm volatile("mma.sync.aligned.m16n8k8.row.col.f32.tf32.tf32.f32 "
                 "{%0,%1,%2,%3}, {%4,%5,%6,%7}, {%8,%9}, {%0,%1,%2,%3};"
                 : "+f"(c0), "+f"(c1), "+f"(c2), "+f"(c3)
                 : "r"(a0), "r"(a1), "r"(a2), "r"(a3), "r"(b0), "r"(b1));
}

#define AS_STRIDE 36
#define BS_STRIDE 136
#define AS_ELEMS (128 * AS_STRIDE)
#define BS_ELEMS (32 * BS_STRIDE)
#define TG_SMEM ((2 * AS_ELEMS + 2 * BS_ELEMS) * 4)

template<bool HAS2, bool BIAS, bool RELU, bool DUAL>
__global__ __launch_bounds__(256, 2) void tgemm(
        const float* __restrict__ A, const float* __restrict__ W,
        const float* __restrict__ A2, const float* __restrict__ W2,
        const float* __restrict__ bias, float* __restrict__ out,
        const float* __restrict__ Wb, float* __restrict__ outb,
        const float* __restrict__ cls5, const float* __restrict__ Wp5,
        const float* __restrict__ Wq5, const float* __restrict__ b1f,
        int M, int K, int N) {
    extern __shared__ unsigned sm[];
    unsigned* AsBase = sm;
    unsigned* BsBase = sm + 2 * AS_ELEMS;
    int t = threadIdx.x;
    int w = t >> 5, lane = t & 31;
    int g = lane >> 2, q = lane & 3;
    int wm = (w >> 2) * 64, wn = (w & 3) * 32;
    int a_row = t >> 3, a_k = (t & 7) * 4;
    int w_k = t >> 5, w_n = (t & 31) * 4;

    int mtiles = (M + 127) >> 7;
    int ntiles = N >> 7;
    int tot = mtiles * ntiles;
    int tot_all = DUAL ? tot * 2 : tot;
    int kslabs = K >> 5;
    int nslab = (HAS2 ? 2 : 1) * kslabs;

    for (int tt = blockIdx.x; tt < tot_all; tt += gridDim.x) {
        bool second = DUAL && (tt >= tot);
        int tile = second ? tt - tot : tt;
        const float* Wsel = second ? Wb : W;
        float* outsel = second ? outb : out;
        int bm = (tile / ntiles) * 128, bn = (tile % ntiles) * 128;

        float acc[4][4][4];
        #pragma unroll
        for (int i = 0; i < 4; i++)
            #pragma unroll
            for (int j = 0; j < 4; j++)
                #pragma unroll
                for (int r = 0; r < 4; r++) acc[i][j][r] = 0.f;

        float4 aP[4], wP[4];
        auto ldA = [&](int j) {
            const float* Ap = (HAS2 && j >= kslabs) ? A2 : A;
            int k0 = (j & (kslabs - 1)) << 5;
            #pragma unroll
            for (int ph = 0; ph < 4; ph++) {
                int grow = bm + a_row + ph * 32;
                aP[ph] = make_float4(0.f, 0.f, 0.f, 0.f);
                if (grow < M) aP[ph] = *(const float4*)(Ap + (size_t)grow * K + k0 + a_k);
            }
        };
        auto ldB = [&](int j) {
            const float* Wp = (HAS2 && j >= kslabs) ? W2 : Wsel;
            int k0 = (j & (kslabs - 1)) << 5;
            #pragma unroll
            for (int ph = 0; ph < 4; ph++)
                wP[ph] = *(const float4*)(Wp + (size_t)(k0 + w_k + ph * 8) * N + bn + w_n);
        };
        auto stStage = [&](int st) {
            unsigned* As = AsBase + st * AS_ELEMS;
            unsigned* Bs = BsBase + st * BS_ELEMS;
            #pragma unroll
            for (int ph = 0; ph < 4; ph++) {
                unsigned* p = &As[(a_row + ph * 32) * AS_STRIDE + a_k];
                p[0] = f2tf32(aP[ph].x); p[1] = f2tf32(aP[ph].y);
                p[2] = f2tf32(aP[ph].z); p[3] = f2tf32(aP[ph].w);
                unsigned* pw = &Bs[(w_k + ph * 8) * BS_STRIDE + w_n];
                pw[0] = f2tf32(wP[ph].x); pw[1] = f2tf32(wP[ph].y);
                pw[2] = f2tf32(wP[ph].z); pw[3] = f2tf32(wP[ph].w);
            }
        };

        ldA(0); ldB(0);
        stStage(0);
        __syncthreads();
        if (nslab > 1) ldA(1);

        for (int j = 0; j < nslab; j++) {
            int s = j & 1;
            const unsigned* As = AsBase + s * AS_ELEMS;
            const unsigned* Bs = BsBase + s * BS_ELEMS;
            #pragma unroll
            for (int kk = 0; kk < 32; kk += 8) {
                unsigned af[4][4], bf[4][2];
                #pragma unroll
                for (int mi = 0; mi < 4; mi++) {
                    const unsigned* p = &As[(wm + mi * 16 + g) * AS_STRIDE + kk + q];
                    af[mi][0] = p[0];
                    af[mi][1] = p[8 * AS_STRIDE];
                    af[mi][2] = p[4];
                    af[mi][3] = p[8 * AS_STRIDE + 4];
                }
                #pragma unroll
                for (int ni = 0; ni < 4; ni++) {
                    const unsigned* p = &Bs[(kk + q) * BS_STRIDE + wn + ni * 8 + g];
                    bf[ni][0] = p[0];
                    bf[ni][1] = p[4 * BS_STRIDE];
                }
                #pragma unroll
                for (int mi = 0; mi < 4; mi++)
                    #pragma unroll
                    for (int ni = 0; ni < 4; ni++)
                        mma_tf32(acc[mi][ni][0], acc[mi][ni][1], acc[mi][ni][2], acc[mi][ni][3],
                                 af[mi][0], af[mi][1], af[mi][2], af[mi][3],
                                 bf[ni][0], bf[ni][1]);
            }
            if (j + 1 < nslab) {
                ldB(j + 1);
                stStage(1 - s);
                if (j + 2 < nslab) ldA(j + 2);
            }
            __syncthreads();
        }

        // DUAL: stage rank-5 fold weights (+ b1 for Q) into now-free smem
        float* fw = (float*)sm;         // [5][128]
        float* fb = fw + 5 * 128;       // [128]
        if (DUAL) {
            const float* Wf = second ? Wq5 : Wp5;
            for (int i = t; i < 5 * 128; i += 256) {
                int r = i >> 7, c = i & 127;
                fw[i] = Wf[r * 256 + bn + c];
            }
            if (second) for (int i = t; i < 128; i += 256) fb[i] = b1f[bn + i];
            __syncthreads();
        }

        #pragma unroll
        for (int mi = 0; mi < 4; mi++) {
            int r0 = bm + wm + mi * 16 + g;
            float cA[5], cB[5];
            if (DUAL) {
                #pragma unroll
                for (int i = 0; i < 5; i++) {
                    cA[i] = (r0 < M) ? cls5[(size_t)r0 * 5 + i] : 0.f;
                    cB[i] = (r0 + 8 < M) ? cls5[(size_t)(r0 + 8) * 5 + i] : 0.f;
                }
            }
            #pragma unroll
            for (int ni = 0; ni < 4; ni++) {
                int colL = wn + ni * 8 + q * 2;
                int col = bn + colL;
                float b0 = 0.f, b1v = 0.f;
                if (BIAS) { b0 = bias[col]; b1v = bias[col + 1]; }
                float2 lo, hi;
                lo.x = acc[mi][ni][0] + b0; lo.y = acc[mi][ni][1] + b1v;
                hi.x = acc[mi][ni][2] + b0; hi.y = acc[mi][ni][3] + b1v;
                if (DUAL) {
                    float d0a = 0.f, d1a = 0.f, d0b = 0.f, d1b = 0.f;
                    #pragma unroll
                    for (int i = 0; i < 5; i++) {
                        float w0 = fw[i * 128 + colL], w1 = fw[i * 128 + colL + 1];
                        d0a += cA[i] * w0; d1a += cA[i] * w1;
                        d0b += cB[i] * w0; d1b += cB[i] * w1;
                    }
                    lo.x += d0a; lo.y += d1a;
                    hi.x += d0b; hi.y += d1b;
                    if (second) {
                        float fb0 = fb[colL], fb1 = fb[colL + 1];
                        lo.x += fb0; lo.y += fb1;
                        hi.x += fb0; hi.y += fb1;
                    }
                }
                if (RELU) {
                    lo.x = fmaxf(lo.x, 0.f); lo.y = fmaxf(lo.y, 0.f);
                    hi.x = fmaxf(hi.x, 0.f); hi.y = fmaxf(hi.y, 0.f);
                }
                if (r0 < M)     *(float2*)(outsel + (size_t)r0 * N + col) = lo;
                if (r0 + 8 < M) *(float2*)(outsel + (size_t)(r0 + 8) * N + col) = hi;
            }
        }
        if (DUAL) __syncthreads();
    }
}

// ---------------- node head ----------------
__global__ void node_head_k(const float* __restrict__ h1, const float* __restrict__ npW,
                            const float* __restrict__ npb, const float* __restrict__ g,
                            const float* __restrict__ beta, float* __restrict__ node_pred,
                            float* __restrict__ cls) {
    int warp = (blockIdx.x * blockDim.x + threadIdx.x) >> 5;
    int lane = threadIdx.x & 31;
    if (warp >= NN) return;
    const float* row = h1 + (size_t)warp * D_HID;
    float p[5] = {};
    for (int k = lane; k < D_HID; k += 32) {
        float hv = row[k];
        #pragma unroll
        for (int j = 0; j < 5; j++) p[j] += hv * npW[k * 5 + j];
    }
    #pragma unroll
    for (int off = 16; off; off >>= 1)
        #pragma unroll
        for (int j = 0; j < 5; j++) p[j] += __shfl_xor_sync(0xffffffffu, p[j], off);
    #pragma unroll
    for (int j = 0; j < 5; j++) p[j] += npb[j];
    float mu = (p[0] + p[1] + p[2] + p[3] + p[4]) * 0.2f;
    float var = 0.f;
    #pragma unroll
    for (int j = 0; j < 5; j++) { float t = p[j] - mu; var += t * t; }
    var *= 0.2f;
    float inv = rsqrtf(var + EPS);
    float y[5];
    #pragma unroll
    for (int j = 0; j < 5; j++) y[j] = g[j] * (p[j] - mu) * inv + beta[j];
    float mx = y[0];
    #pragma unroll
    for (int j = 1; j < 5; j++) mx = fmaxf(mx, y[j]);
    float es[5], se = 0.f;
    #pragma unroll
    for (int j = 0; j < 5; j++) { es[j] = __expf(y[j] - mx); se += es[j]; }
    float rse = 1.f / se;
    if (lane == 0) {
        #pragma unroll
        for (int j = 0; j < 5; j++) {
            node_pred[(size_t)warp * 5 + j] = y[j];
            cls[(size_t)warp * 5 + j] = es[j] * rse;
        }
    }
}

// ---------------- edge head: reg weights + cached Q row (CSR dst-grouped) ----------
#define EH_EPW 16
__global__ __launch_bounds__(256, 2) void edge_head_k(
        const float* __restrict__ P, const float* __restrict__ Q,
        const float* __restrict__ efeat, const float* __restrict__ W1,
        const float* __restrict__ g, const float* __restrict__ beta,
        const float* __restrict__ W2, const float* __restrict__ b2,
        float* __restrict__ out) {
    int gw = (blockIdx.x * blockDim.x + threadIdx.x) >> 5;
    int lane = threadIdx.x & 31;
    int f0 = lane * 8;

    float we[6][8];
    #pragma unroll
    for (int i = 0; i < 6; i++) {
        float4 a = *(const float4*)(W1 + (261 + i) * 256 + f0);
        float4 b = *(const float4*)(W1 + (261 + i) * 256 + f0 + 4);
        we[i][0] = a.x; we[i][1] = a.y; we[i][2] = a.z; we[i][3] = a.w;
        we[i][4] = b.x; we[i][5] = b.y; we[i][6] = b.z; we[i][7] = b.w;
    }
    float w2a[8], w2b[8], gv[8], bv[8];
    #pragma unroll
    for (int i = 0; i < 8; i++) {
        w2a[i] = W2[(f0 + i) * 2 + 0];
        w2b[i] = W2[(f0 + i) * 2 + 1];
        gv[i] = g[f0 + i];
        bv[i] = beta[f0 + i];
    }
    float b20 = b2[0], b21 = b2[1];

    int jbase = gw * EH_EPW;
    int d_prev = -1;
    float qc[8];
    #pragma unroll 1
    for (int ii = 0; ii < EH_EPW; ii++) {
        int j = jbase + ii;
        if (j >= EE) break;
        int s = g_csrc[j], d = g_cdst[j], e = g_eid[j];
        if (d != d_prev) {
            float4 qa = *(const float4*)(Q + (size_t)d * 256 + f0);
            float4 qb = *(const float4*)(Q + (size_t)d * 256 + f0 + 4);
            qc[0] = qa.x; qc[1] = qa.y; qc[2] = qa.z; qc[3] = qa.w;
            qc[4] = qb.x; qc[5] = qb.y; qc[6] = qb.z; qc[7] = qb.w;
            d_prev = d;
        }
        float y[8];
        {
            float4 pa = *(const float4*)(P + (size_t)s * 256 + f0);
            float4 pb = *(const float4*)(P + (size_t)s * 256 + f0 + 4);
            y[0] = pa.x + qc[0]; y[1] = pa.y + qc[1]; y[2] = pa.z + qc[2]; y[3] = pa.w + qc[3];
            y[4] = pb.x + qc[4]; y[5] = pb.y + qc[5]; y[6] = pb.z + qc[6]; y[7] = pb.w + qc[7];
        }
        float ev = 0.f;
        if (lane < 6) ev = efeat[(size_t)e * 6 + lane];
        #pragma unroll
        for (int i = 0; i < 6; i++) {
            float ci = __shfl_sync(0xffffffffu, ev, i);
            #pragma unroll
            for (int r = 0; r < 8; r++) y[r] += ci * we[i][r];
        }
        float sum = 0.f;
        #pragma unroll
        for (int i = 0; i < 8; i++) sum += y[i];
        #pragma unroll
        for (int off = 16; off; off >>= 1) sum += __shfl_xor_sync(0xffffffffu, sum, off);
        float mu = sum * (1.f / 256.f);
        float vs = 0.f;
        #pragma unroll
        for (int i = 0; i < 8; i++) { float t = y[i] - mu; vs += t * t; }
        #pragma unroll
        for (int off = 16; off; off >>= 1) vs += __shfl_xor_sync(0xffffffffu, vs, off);
        float inv = rsqrtf(vs * (1.f / 256.f) + EPS);
        float o0 = 0.f, o1 = 0.f;
        #pragma unroll
        for (int i = 0; i < 8; i++) {
            float yn = gv[i] * (y[i] - mu) * inv + bv[i];
            yn = fmaxf(yn, 0.f);
            o0 += yn * w2a[i];
            o1 += yn * w2b[i];
        }
        #pragma unroll
        for (int off = 16; off; off >>= 1) {
            o0 += __shfl_xor_sync(0xffffffffu, o0, off);
            o1 += __shfl_xor_sync(0xffffffffu, o1, off);
        }
        if (lane == 0) {
            out[(size_t)e * 2 + 0] = o0 + b20;
            out[(size_t)e * 2 + 1] = o1 + b21;
        }
    }
}

// ---------------- launch ----------------
static inline int ggrid(int tiles) {
    int passes = (tiles + 295) / 296;
    return (tiles + passes - 1) / passes;
}

extern "C" void kernel_launch(void* const* d_in, const int* in_sizes, int n_in,
                              void* d_out, int out_size) {
    const float* h        = (const float*)d_in[0];
    const float* efeat    = (const float*)d_in[1];
    const int*   src      = (const int*)  d_in[2];
    const int*   dst      = (const int*)  d_in[3];
    const float* encWpool = (const float*)d_in[4];
    const float* encbpool = (const float*)d_in[5];
    const float* encWself = (const float*)d_in[6];
    const float* encbself = (const float*)d_in[7];
    const float* encWneigh= (const float*)d_in[8];
    const float* npW      = (const float*)d_in[9];
    const float* npb      = (const float*)d_in[10];
    const float* npg      = (const float*)d_in[11];
    const float* npbeta   = (const float*)d_in[12];
    const float* epW1     = (const float*)d_in[13];
    const float* epb1     = (const float*)d_in[14];
    const float* epg      = (const float*)d_in[15];
    const float* epbeta   = (const float*)d_in[16];
    const float* epW2     = (const float*)d_in[17];
    const float* epb2     = (const float*)d_in[18];
    const float* decWpool = (const float*)d_in[19];
    const float* decbpool = (const float*)d_in[20];
    const float* decWself = (const float*)d_in[21];
    const float* decbself = (const float*)d_in[22];
    const float* decWneigh= (const float*)d_in[23];

    float* out       = (float*)d_out;
    float* node_pred = out;
    float* edge_pred = out + NN * 5;
    float* h2        = out + NN * 5 + EE * 2;

    float *m1, *agg1, *h1, *cls, *P, *Q, *m2, *agg2;
    cudaGetSymbolAddress((void**)&m1,  g_m1);
    cudaGetSymbolAddress((void**)&agg1,g_agg1);
    cudaGetSymbolAddress((void**)&h1,  g_h1);
    cudaGetSymbolAddress((void**)&cls, g_cls);
    cudaGetSymbolAddress((void**)&P,   g_P);
    cudaGetSymbolAddress((void**)&Q,   g_Q);
    cudaGetSymbolAddress((void**)&m2,  g_m2);
    cudaGetSymbolAddress((void**)&agg2,g_agg2);

    static cudaStream_t s2 = nullptr;
    static cudaEvent_t evFork1 = nullptr, evJoin1 = nullptr, evFork2 = nullptr,
                       evJoin2 = nullptr;
    if (s2 == nullptr) {
        cudaStreamCreateWithFlags(&s2, cudaStreamNonBlocking);
        cudaEventCreateWithFlags(&evFork1, cudaEventDisableTiming);
        cudaEventCreateWithFlags(&evJoin1, cudaEventDisableTiming);
        cudaEventCreateWithFlags(&evFork2, cudaEventDisableTiming);
        cudaEventCreateWithFlags(&evJoin2, cudaEventDisableTiming);
        cudaFuncSetAttribute(tgemm<false, true,  true,  false>, cudaFuncAttributeMaxDynamicSharedMemorySize, TG_SMEM);
        cudaFuncSetAttribute(tgemm<true,  true,  true,  false>, cudaFuncAttributeMaxDynamicSharedMemorySize, TG_SMEM);
        cudaFuncSetAttribute(tgemm<false, false, false, true >, cudaFuncAttributeMaxDynamicSharedMemorySize, TG_SMEM);
    }

    // fork 1: the ENTIRE CSR chain runs on s2, overlapped with the enc-pool GEMM
    cudaEventRecord(evFork1, 0);
    cudaStreamWaitEvent(s2, evFork1, 0);

    // main: encoder pool GEMM (needs only h)
    tgemm<false, true, true, false><<<ggrid(235), 256, TG_SMEM>>>(
        h, encWpool, nullptr, nullptr, encbpool, m1, nullptr, nullptr,
        nullptr, nullptr, nullptr, nullptr, NN, D_IN, D_IN);

    // s2: CSR build (zero -> hist -> scan -> fill)
    csr_zero_k<<<(NN + 255) / 256, 256, 0, s2>>>();
    csr_hist_k<<<(EE + 255) / 256, 256, 0, s2>>>(dst);
    csr_scan_k<<<1, 1024, 0, s2>>>();
    csr_fill_k<<<(EE + 255) / 256, 256, 0, s2>>>(src, dst);
    cudaEventRecord(evJoin1, s2);
    cudaStreamWaitEvent(0, evJoin1, 0);

    gather_max_128<<<(NN * 32 + 255) / 256, 256>>>(m1, agg1);

    tgemm<true, true, true, false><<<ggrid(470), 256, TG_SMEM>>>(
        h, encWself, agg1, encWneigh, encbself, h1, nullptr, nullptr,
        nullptr, nullptr, nullptr, nullptr, NN, D_IN, D_HID);

    // node head on main (cls must precede the fused P/Q GEMM)
    node_head_k<<<(NN * 32 + 255) / 256, 256>>>(h1, npW, npb, npg, npbeta, node_pred, cls);

    // fork 2: decoder branch on s2, edge branch on main (full grids)
    cudaEventRecord(evFork2, 0);
    cudaStreamWaitEvent(s2, evFork2, 0);

    tgemm<false, true, true, false><<<ggrid(470), 256, TG_SMEM, s2>>>(
        h1, decWpool, nullptr, nullptr, decbpool, m2, nullptr, nullptr,
        nullptr, nullptr, nullptr, nullptr, NN, D_HID, D_HID);
    gather_max_256<<<(NN * 32 + 255) / 256, 256, 0, s2>>>(m2, agg2);
    tgemm<true, true, true, false><<<ggrid(235), 256, TG_SMEM, s2>>>(
        h1, decWself, agg2, decWneigh, decbself, h2, nullptr, nullptr,
        nullptr, nullptr, nullptr, nullptr, NN, D_HID, D_IN);
    cudaEventRecord(evJoin2, s2);

    // edge branch (main): fused P/Q GEMM (fold inlined) -> edge head
    tgemm<false, false, false, true><<<ggrid(940), 256, TG_SMEM>>>(
        h1, epW1, nullptr, nullptr, nullptr, P, epW1 + 267 * 256, Q,
        cls, epW1 + 256 * 256, epW1 + 523 * 256, epb1, NN, D_HID, D_HID);
    edge_head_k<<<(EE + EH_EPW * 8 - 1) / (EH_EPW * 8), 256>>>(
        P, Q, efeat, epW1, epg, epbeta, epW2, epb2, edge_pred);

    // join decoder branch back into main
    cudaStreamWaitEvent(0, evJoin2, 0);
}

// round 16
// speedup vs baseline: 1.0954x; 1.0041x over previous
#include <cuda_runtime.h>
#include <cuda_bf16.h>
#include <math.h>

#define NN 30000
#define EE 480000
#define D_IN 128
#define D_HID 256
#define EPS 1e-5f

// ---------------- scratch (device globals; no allocation) ----------------
__device__ float g_m1 [NN * D_IN];
__device__ float g_agg1[NN * D_IN];
__device__ float g_h1 [NN * D_HID];
__device__ float g_cls[NN * 5];
__device__ float g_P  [NN * D_HID];
__device__ float g_Q  [NN * D_HID];
__device__ float g_m2 [NN * D_HID];
__device__ float g_agg2[NN * D_HID];
__device__ int g_deg [NN];
__device__ int g_cur [NN];
__device__ int g_rowstart[NN + 1];
__device__ int g_csrc[EE];
__device__ int g_cdst[EE];
__device__ int g_eid [EE];

// ---------------- CSR build ----------------
__global__ void csr_zero_k() {
    int i = blockIdx.x * blockDim.x + threadIdx.x;
    if (i < NN) { g_deg[i] = 0; g_cur[i] = 0; }
}
__global__ void csr_hist_k(const int* __restrict__ dst) {
    int e = blockIdx.x * blockDim.x + threadIdx.x;
    if (e < EE) atomicAdd(&g_deg[dst[e]], 1);
}
// shuffle-based two-level scan: 2 barriers total
__global__ void csr_scan_k() {
    __shared__ int wsum[32];
    int t = threadIdx.x;                  // 1024 threads
    const int C = (NN + 1023) / 1024;     // 30
    int base = t * C;
    int lsum = 0;
    #pragma unroll
    for (int i = 0; i < C; i++) { int idx = base + i; if (idx < NN) lsum += g_deg[idx]; }
    int lane = t & 31, wid = t >> 5;
    // warp-inclusive scan
    int x = lsum;
    #pragma unroll
    for (int off = 1; off < 32; off <<= 1) {
        int y = __shfl_up_sync(0xffffffffu, x, off);
        if (lane >= off) x += y;
    }
    if (lane == 31) wsum[wid] = x;
    __syncthreads();
    if (wid == 0) {
        int wv = wsum[lane];
        #pragma unroll
        for (int off = 1; off < 32; off <<= 1) {
            int y = __shfl_up_sync(0xffffffffu, wv, off);
            if (lane >= off) wv += y;
        }
        wsum[lane] = wv;
    }
    __syncthreads();
    int excl = (x - lsum) + (wid > 0 ? wsum[wid - 1] : 0);
    int run = excl;
    for (int i = 0; i < C; i++) {
        int idx = base + i;
        if (idx < NN) { g_rowstart[idx] = run; run += g_deg[idx]; }
    }
    if (t == 1023) g_rowstart[NN] = EE;
}
__global__ void csr_fill_k(const int* __restrict__ src, const int* __restrict__ dst) {
    int e = blockIdx.x * blockDim.x + threadIdx.x;
    if (e >= EE) return;
    int d = dst[e];
    int pos = g_rowstart[d] + atomicAdd(&g_cur[d], 1);
    g_csrc[pos] = src[e];
    g_cdst[pos] = d;
    g_eid[pos]  = e;
}

// ---------------- gather segment-max ----------------
__global__ void gather_max_128(const float* __restrict__ msg, float* __restrict__ agg) {
    int warp = (blockIdx.x * blockDim.x + threadIdx.x) >> 5;
    int lane = threadIdx.x & 31;
    if (warp >= NN) return;
    int rs = g_rowstart[warp], re = g_rowstart[warp + 1];
    float4 v = make_float4(0.f, 0.f, 0.f, 0.f);
    for (int j = rs; j < re; j++) {
        int s = g_csrc[j];
        float4 m = *(const float4*)(msg + (size_t)s * 128 + lane * 4);
        v.x = fmaxf(v.x, m.x); v.y = fmaxf(v.y, m.y);
        v.z = fmaxf(v.z, m.z); v.w = fmaxf(v.w, m.w);
    }
    *(float4*)(agg + (size_t)warp * 128 + lane * 4) = v;
}
__global__ void gather_max_256(const float* __restrict__ msg, float* __restrict__ agg) {
    int warp = (blockIdx.x * blockDim.x + threadIdx.x) >> 5;
    int lane = threadIdx.x & 31;
    if (warp >= NN) return;
    int rs = g_rowstart[warp], re = g_rowstart[warp + 1];
    float4 v0 = make_float4(0.f, 0.f, 0.f, 0.f);
    float4 v1 = v0;
    for (int j = rs; j < re; j++) {
        int s = g_csrc[j];
        const float* row = msg + (size_t)s * 256;
        float4 a = *(const float4*)(row + lane * 4);
        float4 b = *(const float4*)(row + 128 + lane * 4);
        v0.x = fmaxf(v0.x, a.x); v0.y = fmaxf(v0.y, a.y);
        v0.z = fmaxf(v0.z, a.z); v0.w = fmaxf(v0.w, a.w);
        v1.x = fmaxf(v1.x, b.x); v1.y = fmaxf(v1.y, b.y);
        v1.z = fmaxf(v1.z, b.z); v1.w = fmaxf(v1.w, b.w);
    }
    *(float4*)(agg + (size_t)warp * 256 + lane * 4) = v0;
    *(float4*)(agg + (size_t)warp * 256 + 128 + lane * 4) = v1;
}

// ---------------- tf32 GEMM: persistent + 2-stage (R9/R13-proven, FROZEN) ----------
__device__ __forceinline__ unsigned f2tf32(float v) {
    unsigned r;
    asm("cvt.rna.tf32.f32 %0, %1;" : "=r"(r) : "f"(v));
    return r;
}
__device__ __forceinline__ void mma_tf32(float& c0, float& c1, float& c2, float& c3,
                                         unsigned a0, unsigned a1, unsigned a2, unsigned a3,
                                         unsigned b0, unsigned b1) {
    asm volatile("mma.sync.aligned.m16n8k8.row.col.f32.tf32.tf32.f32 "
                 "{%0,%1,%2,%3}, {%4,%5,%6,%7}, {%8,%9}, {%0,%1,%2,%3};"
                 : "+f"(c0), "+f"(c1), "+f"(c2), "+f"(c3)
                 : "r"(a0), "r"(a1), "r"(a2), "r"(a3), "r"(b0), "r"(b1));
}

#define AS_STRIDE 36
#define BS_STRIDE 136
#define AS_ELEMS (128 * AS_STRIDE)
#define BS_ELEMS (32 * BS_STRIDE)
#define TG_SMEM ((2 * AS_ELEMS + 2 * BS_ELEMS) * 4)

template<bool HAS2, bool BIAS, bool RELU, bool DUAL>
__global__ __launch_bounds__(256, 2) void tgemm(
        const float* __restrict__ A, const float* __restrict__ W,
        const float* __restrict__ A2, const float* __restrict__ W2,
        const float* __restrict__ bias, float* __restrict__ out,
        const float* __restrict__ Wb, float* __restrict__ outb,
        const float* __restrict__ cls5, const float* __restrict__ Wp5,
        const float* __restrict__ Wq5, const float* __restrict__ b1f,
        int M, int K, int N) {
    extern __shared__ unsigned sm[];
    unsigned* AsBase = sm;
    unsigned* BsBase = sm + 2 * AS_ELEMS;
    int t = threadIdx.x;
    int w = t >> 5, lane = t & 31;
    int g = lane >> 2, q = lane & 3;
    int wm = (w >> 2) * 64, wn = (w & 3) * 32;
    int a_row = t >> 3, a_k = (t & 7) * 4;
    int w_k = t >> 5, w_n = (t & 31) * 4;

    int mtiles = (M + 127) >> 7;
    int ntiles = N >> 7;
    int tot = mtiles * ntiles;
    int tot_all = DUAL ? tot * 2 : tot;
    int kslabs = K >> 5;
    int nslab = (HAS2 ? 2 : 1) * kslabs;

    for (int tt = blockIdx.x; tt < tot_all; tt += gridDim.x) {
        bool second = DUAL && (tt >= tot);
        int tile = second ? tt - tot : tt;
        const float* Wsel = second ? Wb : W;
        float* outsel = second ? outb : out;
        int bm = (tile / ntiles) * 128, bn = (tile % ntiles) * 128;

        float acc[4][4][4];
        #pragma unroll
        for (int i = 0; i < 4; i++)
            #pragma unroll
            for (int j = 0; j < 4; j++)
                #pragma unroll
                for (int r = 0; r < 4; r++) acc[i][j][r] = 0.f;

        float4 aP[4], wP[4];
        auto ldA = [&](int j) {
            const float* Ap = (HAS2 && j >= kslabs) ? A2 : A;
            int k0 = (j & (kslabs - 1)) << 5;
            #pragma unroll
            for (int ph = 0; ph < 4; ph++) {
                int grow = bm + a_row + ph * 32;
                aP[ph] = make_float4(0.f, 0.f, 0.f, 0.f);
                if (grow < M) aP[ph] = *(const float4*)(Ap + (size_t)grow * K + k0 + a_k);
            }
        };
        auto ldB = [&](int j) {
            const float* Wp = (HAS2 && j >= kslabs) ? W2 : Wsel;
            int k0 = (j & (kslabs - 1)) << 5;
            #pragma unroll
            for (int ph = 0; ph < 4; ph++)
                wP[ph] = *(const float4*)(Wp + (size_t)(k0 + w_k + ph * 8) * N + bn + w_n);
        };
        auto stStage = [&](int st) {
            unsigned* As = AsBase + st * AS_ELEMS;
            unsigned* Bs = BsBase + st * BS_ELEMS;
            #pragma unroll
            for (int ph = 0; ph < 4; ph++) {
                unsigned* p = &As[(a_row + ph * 32) * AS_STRIDE + a_k];
                p[0] = f2tf32(aP[ph].x); p[1] = f2tf32(aP[ph].y);
                p[2] = f2tf32(aP[ph].z); p[3] = f2tf32(aP[ph].w);
                unsigned* pw = &Bs[(w_k + ph * 8) * BS_STRIDE + w_n];
                pw[0] = f2tf32(wP[ph].x); pw[1] = f2tf32(wP[ph].y);
                pw[2] = f2tf32(wP[ph].z); pw[3] = f2tf32(wP[ph].w);
            }
        };

        ldA(0); ldB(0);
        stStage(0);
        __syncthreads();
        if (nslab > 1) ldA(1);

        for (int j = 0; j < nslab; j++) {
            int s = j & 1;
            const unsigned* As = AsBase + s * AS_ELEMS;
            const unsigned* Bs = BsBase + s * BS_ELEMS;
            #pragma unroll
            for (int kk = 0; kk < 32; kk += 8) {
                unsigned af[4][4], bf[4][2];
                #pragma unroll
                for (int mi = 0; mi < 4; mi++) {
                    const unsigned* p = &As[(wm + mi * 16 + g) * AS_STRIDE + kk + q];
                    af[mi][0] = p[0];
                    af[mi][1] = p[8 * AS_STRIDE];
                    af[mi][2] = p[4];
                    af[mi][3] = p[8 * AS_STRIDE + 4];
                }
                #pragma unroll
                for (int ni = 0; ni < 4; ni++) {
                    const unsigned* p = &Bs[(kk + q) * BS_STRIDE + wn + ni * 8 + g];
                    bf[ni][0] = p[0];
                    bf[ni][1] = p[4 * BS_STRIDE];
                }
                #pragma unroll
                for (int mi = 0; mi < 4; mi++)
                    #pragma unroll
                    for (int ni = 0; ni < 4; ni++)
                        mma_tf32(acc[mi][ni][0], acc[mi][ni][1], acc[mi][ni][2], acc[mi][ni][3],
                                 af[mi][0], af[mi][1], af[mi][2], af[mi][3],
                                 bf[ni][0], bf[ni][1]);
            }
            if (j + 1 < nslab) {
                ldB(j + 1);
                stStage(1 - s);
                if (j + 2 < nslab) ldA(j + 2);
            }
            __syncthreads();
        }

        // DUAL: stage rank-5 fold weights (+ b1 for Q) into now-free smem
        float* fw = (float*)sm;         // [5][128]
        float* fb = fw + 5 * 128;       // [128]
        if (DUAL) {
            const float* Wf = second ? Wq5 : Wp5;
            for (int i = t; i < 5 * 128; i += 256) {
                int r = i >> 7, c = i & 127;
                fw[i] = Wf[r * 256 + bn + c];
            }
            if (second) for (int i = t; i < 128; i += 256) fb[i] = b1f[bn + i];
            __syncthreads();
        }

        #pragma unroll
        for (int mi = 0; mi < 4; mi++) {
            int r0 = bm + wm + mi * 16 + g;
            float cA[5], cB[5];
            if (DUAL) {
                #pragma unroll
                for (int i = 0; i < 5; i++) {
                    cA[i] = (r0 < M) ? cls5[(size_t)r0 * 5 + i] : 0.f;
                    cB[i] = (r0 + 8 < M) ? cls5[(size_t)(r0 + 8) * 5 + i] : 0.f;
                }
            }
            #pragma unroll
            for (int ni = 0; ni < 4; ni++) {
                int colL = wn + ni * 8 + q * 2;
                int col = bn + colL;
                float b0 = 0.f, b1v = 0.f;
                if (BIAS) { b0 = bias[col]; b1v = bias[col + 1]; }
                float2 lo, hi;
                lo.x = acc[mi][ni][0] + b0; lo.y = acc[mi][ni][1] + b1v;
                hi.x = acc[mi][ni][2] + b0; hi.y = acc[mi][ni][3] + b1v;
                if (DUAL) {
                    float d0a = 0.f, d1a = 0.f, d0b = 0.f, d1b = 0.f;
                    #pragma unroll
                    for (int i = 0; i < 5; i++) {
                        float w0 = fw[i * 128 + colL], w1 = fw[i * 128 + colL + 1];
                        d0a += cA[i] * w0; d1a += cA[i] * w1;
                        d0b += cB[i] * w0; d1b += cB[i] * w1;
                    }
                    lo.x += d0a; lo.y += d1a;
                    hi.x += d0b; hi.y += d1b;
                    if (second) {
                        float fb0 = fb[colL], fb1 = fb[colL + 1];
                        lo.x += fb0; lo.y += fb1;
                        hi.x += fb0; hi.y += fb1;
                    }
                }
                if (RELU) {
                    lo.x = fmaxf(lo.x, 0.f); lo.y = fmaxf(lo.y, 0.f);
                    hi.x = fmaxf(hi.x, 0.f); hi.y = fmaxf(hi.y, 0.f);
                }
                if (r0 < M)     *(float2*)(outsel + (size_t)r0 * N + col) = lo;
                if (r0 + 8 < M) *(float2*)(outsel + (size_t)(r0 + 8) * N + col) = hi;
            }
        }
        if (DUAL) __syncthreads();
    }
}

// ---------------- node head ----------------
__global__ void node_head_k(const float* __restrict__ h1, const float* __restrict__ npW,
                            const float* __restrict__ npb, const float* __restrict__ g,
                            const float* __restrict__ beta, float* __restrict__ node_pred,
                            float* __restrict__ cls) {
    int warp = (blockIdx.x * blockDim.x + threadIdx.x) >> 5;
    int lane = threadIdx.x & 31;
    if (warp >= NN) return;
    const float* row = h1 + (size_t)warp * D_HID;
    float p[5] = {};
    for (int k = lane; k < D_HID; k += 32) {
        float hv = row[k];
        #pragma unroll
        for (int j = 0; j < 5; j++) p[j] += hv * npW[k * 5 + j];
    }
    #pragma unroll
    for (int off = 16; off; off >>= 1)
        #pragma unroll
        for (int j = 0; j < 5; j++) p[j] += __shfl_xor_sync(0xffffffffu, p[j], off);
    #pragma unroll
    for (int j = 0; j < 5; j++) p[j] += npb[j];
    float mu = (p[0] + p[1] + p[2] + p[3] + p[4]) * 0.2f;
    float var = 0.f;
    #pragma unroll
    for (int j = 0; j < 5; j++) { float t = p[j] - mu; var += t * t; }
    var *= 0.2f;
    float inv = rsqrtf(var + EPS);
    float y[5];
    #pragma unroll
    for (int j = 0; j < 5; j++) y[j] = g[j] * (p[j] - mu) * inv + beta[j];
    float mx = y[0];
    #pragma unroll
    for (int j = 1; j < 5; j++) mx = fmaxf(mx, y[j]);
    float es[5], se = 0.f;
    #pragma unroll
    for (int j = 0; j < 5; j++) { es[j] = __expf(y[j] - mx); se += es[j]; }
    float rse = 1.f / se;
    if (lane == 0) {
        #pragma unroll
        for (int j = 0; j < 5; j++) {
            node_pred[(size_t)warp * 5 + j] = y[j];
            cls[(size_t)warp * 5 + j] = es[j] * rse;
        }
    }
}

// ---------------- edge head: reg weights + cached Q row (CSR dst-grouped) ----------
#define EH_EPW 16
__global__ __launch_bounds__(256, 2) void edge_head_k(
        const float* __restrict__ P, const float* __restrict__ Q,
        const float* __restrict__ efeat, const float* __restrict__ W1,
        const float* __restrict__ g, const float* __restrict__ beta,
        const float* __restrict__ W2, const float* __restrict__ b2,
        float* __restrict__ out) {
    int gw = (blockIdx.x * blockDim.x + threadIdx.x) >> 5;
    int lane = threadIdx.x & 31;
    int f0 = lane * 8;

    float we[6][8];
    #pragma unroll
    for (int i = 0; i < 6; i++) {
        float4 a = *(const float4*)(W1 + (261 + i) * 256 + f0);
        float4 b = *(const float4*)(W1 + (261 + i) * 256 + f0 + 4);
        we[i][0] = a.x; we[i][1] = a.y; we[i][2] = a.z; we[i][3] = a.w;
        we[i][4] = b.x; we[i][5] = b.y; we[i][6] = b.z; we[i][7] = b.w;
    }
    float w2a[8], w2b[8], gv[8], bv[8];
    #pragma unroll
    for (int i = 0; i < 8; i++) {
        w2a[i] = W2[(f0 + i) * 2 + 0];
        w2b[i] = W2[(f0 + i) * 2 + 1];
        gv[i] = g[f0 + i];
        bv[i] = beta[f0 + i];
    }
    float b20 = b2[0], b21 = b2[1];

    int jbase = gw * EH_EPW;
    int d_prev = -1;
    float qc[8];
    #pragma unroll 1
    for (int ii = 0; ii < EH_EPW; ii++) {
        int j = jbase + ii;
        if (j >= EE) break;
        int s = g_csrc[j], d = g_cdst[j], e = g_eid[j];
        if (d != d_prev) {
            float4 qa = *(const float4*)(Q + (size_t)d * 256 + f0);
            float4 qb = *(const float4*)(Q + (size_t)d * 256 + f0 + 4);
            qc[0] = qa.x; qc[1] = qa.y; qc[2] = qa.z; qc[3] = qa.w;
            qc[4] = qb.x; qc[5] = qb.y; qc[6] = qb.z; qc[7] = qb.w;
            d_prev = d;
        }
        float y[8];
        {
            float4 pa = *(const float4*)(P + (size_t)s * 256 + f0);
            float4 pb = *(const float4*)(P + (size_t)s * 256 + f0 + 4);
            y[0] = pa.x + qc[0]; y[1] = pa.y + qc[1]; y[2] = pa.z + qc[2]; y[3] = pa.w + qc[3];
            y[4] = pb.x + qc[4]; y[5] = pb.y + qc[5]; y[6] = pb.z + qc[6]; y[7] = pb.w + qc[7];
        }
        float ev = 0.f;
        if (lane < 6) ev = efeat[(size_t)e * 6 + lane];
        #pragma unroll
        for (int i = 0; i < 6; i++) {
            float ci = __shfl_sync(0xffffffffu, ev, i);
            #pragma unroll
            for (int r = 0; r < 8; r++) y[r] += ci * we[i][r];
        }
        float sum = 0.f;
        #pragma unroll
        for (int i = 0; i < 8; i++) sum += y[i];
        #pragma unroll
        for (int off = 16; off; off >>= 1) sum += __shfl_xor_sync(0xffffffffu, sum, off);
        float mu = sum * (1.f / 256.f);
        float vs = 0.f;
        #pragma unroll
        for (int i = 0; i < 8; i++) { float t = y[i] - mu; vs += t * t; }
        #pragma unroll
        for (int off = 16; off; off >>= 1) vs += __shfl_xor_sync(0xffffffffu, vs, off);
        float inv = rsqrtf(vs * (1.f / 256.f) + EPS);
        float o0 = 0.f, o1 = 0.f;
        #pragma unroll
        for (int i = 0; i < 8; i++) {
            float yn = gv[i] * (y[i] - mu) * inv + bv[i];
            yn = fmaxf(yn, 0.f);
            o0 += yn * w2a[i];
            o1 += yn * w2b[i];
        }
        #pragma unroll
        for (int off = 16; off; off >>= 1) {
            o0 += __shfl_xor_sync(0xffffffffu, o0, off);
            o1 += __shfl_xor_sync(0xffffffffu, o1, off);
        }
        if (lane == 0) {
            out[(size_t)e * 2 + 0] = o0 + b20;
            out[(size_t)e * 2 + 1] = o1 + b21;
        }
    }
}

// ---------------- launch ----------------
static inline int ggrid(int tiles) {
    int passes = (tiles + 295) / 296;
    return (tiles + passes - 1) / passes;
}

extern "C" void kernel_launch(void* const* d_in, const int* in_sizes, int n_in,
                              void* d_out, int out_size) {
    const float* h        = (const float*)d_in[0];
    const float* efeat    = (const float*)d_in[1];
    const int*   src      = (const int*)  d_in[2];
    const int*   dst      = (const int*)  d_in[3];
    const float* encWpool = (const float*)d_in[4];
    const float* encbpool = (const float*)d_in[5];
    const float* encWself = (const float*)d_in[6];
    const float* encbself = (const float*)d_in[7];
    const float* encWneigh= (const float*)d_in[8];
    const float* npW      = (const float*)d_in[9];
    const float* npb      = (const float*)d_in[10];
    const float* npg      = (const float*)d_in[11];
    const float* npbeta   = (const float*)d_in[12];
    const float* epW1     = (const float*)d_in[13];
    const float* epb1     = (const float*)d_in[14];
    const float* epg      = (const float*)d_in[15];
    const float* epbeta   = (const float*)d_in[16];
    const float* epW2     = (const float*)d_in[17];
    const float* epb2     = (const float*)d_in[18];
    const float* decWpool = (const float*)d_in[19];
    const float* decbpool = (const float*)d_in[20];
    const float* decWself = (const float*)d_in[21];
    const float* decbself = (const float*)d_in[22];
    const float* decWneigh= (const float*)d_in[23];

    float* out       = (float*)d_out;
    float* node_pred = out;
    float* edge_pred = out + NN * 5;
    float* h2        = out + NN * 5 + EE * 2;

    float *m1, *agg1, *h1, *cls, *P, *Q, *m2, *agg2;
    cudaGetSymbolAddress((void**)&m1,  g_m1);
    cudaGetSymbolAddress((void**)&agg1,g_agg1);
    cudaGetSymbolAddress((void**)&h1,  g_h1);
    cudaGetSymbolAddress((void**)&cls, g_cls);
    cudaGetSymbolAddress((void**)&P,   g_P);
    cudaGetSymbolAddress((void**)&Q,   g_Q);
    cudaGetSymbolAddress((void**)&m2,  g_m2);
    cudaGetSymbolAddress((void**)&agg2,g_agg2);

    static cudaStream_t s2 = nullptr;
    static cudaEvent_t evFork1 = nullptr, evJoin1 = nullptr, evFork2 = nullptr,
                       evJoin2 = nullptr;
    if (s2 == nullptr) {
        cudaStreamCreateWithFlags(&s2, cudaStreamNonBlocking);
        cudaEventCreateWithFlags(&evFork1, cudaEventDisableTiming);
        cudaEventCreateWithFlags(&evJoin1, cudaEventDisableTiming);
        cudaEventCreateWithFlags(&evFork2, cudaEventDisableTiming);
        cudaEventCreateWithFlags(&evJoin2, cudaEventDisableTiming);
        cudaFuncSetAttribute(tgemm<false, true,  true,  false>, cudaFuncAttributeMaxDynamicSharedMemorySize, TG_SMEM);
        cudaFuncSetAttribute(tgemm<true,  true,  true,  false>, cudaFuncAttributeMaxDynamicSharedMemorySize, TG_SMEM);
        cudaFuncSetAttribute(tgemm<false, false, false, true >, cudaFuncAttributeMaxDynamicSharedMemorySize, TG_SMEM);
    }

    // fork 1: the ENTIRE CSR chain runs on s2, overlapped with the enc-pool GEMM
    cudaEventRecord(evFork1, 0);
    cudaStreamWaitEvent(s2, evFork1, 0);

    // main: encoder pool GEMM (needs only h)
    tgemm<false, true, true, false><<<ggrid(235), 256, TG_SMEM>>>(
        h, encWpool, nullptr, nullptr, encbpool, m1, nullptr, nullptr,
        nullptr, nullptr, nullptr, nullptr, NN, D_IN, D_IN);

    // s2: CSR build (zero -> hist -> scan -> fill)
    csr_zero_k<<<(NN + 255) / 256, 256, 0, s2>>>();
    csr_hist_k<<<(EE + 255) / 256, 256, 0, s2>>>(dst);
    csr_scan_k<<<1, 1024, 0, s2>>>();
    csr_fill_k<<<(EE + 255) / 256, 256, 0, s2>>>(src, dst);
    cudaEventRecord(evJoin1, s2);
    cudaStreamWaitEvent(0, evJoin1, 0);

    gather_max_128<<<(NN * 32 + 255) / 256, 256>>>(m1, agg1);

    tgemm<true, true, true, false><<<ggrid(470), 256, TG_SMEM>>>(
        h, encWself, agg1, encWneigh, encbself, h1, nullptr, nullptr,
        nullptr, nullptr, nullptr, nullptr, NN, D_IN, D_HID);

    // node head on main (cls must precede the fused P/Q GEMM)
    node_head_k<<<(NN * 32 + 255) / 256, 256>>>(h1, npW, npb, npg, npbeta, node_pred, cls);

    // fork 2: decoder branch on s2, edge branch on main (full grids)
    cudaEventRecord(evFork2, 0);
    cudaStreamWaitEvent(s2, evFork2, 0);

    tgemm<false, true, true, false><<<ggrid(470), 256, TG_SMEM, s2>>>(
        h1, decWpool, nullptr, nullptr, decbpool, m2, nullptr, nullptr,
        nullptr, nullptr, nullptr, nullptr, NN, D_HID, D_HID);
    gather_max_256<<<(NN * 32 + 255) / 256, 256, 0, s2>>>(m2, agg2);
    tgemm<true, true, true, false><<<ggrid(235), 256, TG_SMEM, s2>>>(
        h1, decWself, agg2, decWneigh, decbself, h2, nullptr, nullptr,
        nullptr, nullptr, nullptr, nullptr, NN, D_HID, D_IN);
    cudaEventRecord(evJoin2, s2);

    // edge branch (main): fused P/Q GEMM (fold inlined) -> edge head
    tgemm<false, false, false, true><<<ggrid(940), 256, TG_SMEM>>>(
        h1, epW1, nullptr, nullptr, nullptr, P, epW1 + 267 * 256, Q,
        cls, epW1 + 256 * 256, epW1 + 523 * 256, epb1, NN, D_HID, D_HID);
    edge_head_k<<<(EE + EH_EPW * 8 - 1) / (EH_EPW * 8), 256>>>(
        P, Q, efeat, epW1, epg, epbeta, epW2, epb2, edge_pred);

    // join decoder branch back into main
    cudaStreamWaitEvent(0, evJoin2, 0);
}

// round 17
// speedup vs baseline: 1.0967x; 1.0012x over previous
#include <cuda_runtime.h>
#include <cuda_bf16.h>
#include <math.h>

#define NN 30000
#define EE 480000
#define D_IN 128
#define D_HID 256
#define EPS 1e-5f

// ---------------- scratch (device globals; no allocation) ----------------
__device__ float g_m1 [NN * D_IN];
__device__ float g_agg1[NN * D_IN];
__device__ float g_h1 [NN * D_HID];
__device__ float g_cls[NN * 5];
__device__ float g_P  [NN * D_HID];
__device__ float g_Q  [NN * D_HID];
__device__ float g_m2 [NN * D_HID];
__device__ float g_agg2[NN * D_HID];
__device__ int g_deg [NN];
__device__ int g_cur [NN];
__device__ int g_rowstart[NN + 1];
__device__ int g_csrc[EE];
__device__ int g_cdst[EE];
__device__ int g_eid [EE];

// ---------------- CSR build ----------------
__global__ void csr_zero_k() {
    int i = blockIdx.x * blockDim.x + threadIdx.x;
    if (i < NN) { g_deg[i] = 0; g_cur[i] = 0; }
}
__global__ void csr_hist_k(const int* __restrict__ dst) {
    int e = blockIdx.x * blockDim.x + threadIdx.x;
    if (e < EE) atomicAdd(&g_deg[dst[e]], 1);
}
// chunk-interleaved block scan: every global access coalesced
__global__ void csr_scan_k() {
    __shared__ int wsum[32];
    int t = threadIdx.x, lane = t & 31, wid = t >> 5;
    const int CH = (NN + 1023) / 1024;   // 30 chunks of 1024
    int carry = 0;                        // running offset (uniform across block)
    for (int c = 0; c < CH; c++) {
        int idx = c * 1024 + t;           // coalesced
        int v = (idx < NN) ? g_deg[idx] : 0;
        // warp-inclusive scan
        int x = v;
        #pragma unroll
        for (int off = 1; off < 32; off <<= 1) {
            int y = __shfl_up_sync(0xffffffffu, x, off);
            if (lane >= off) x += y;
        }
        if (lane == 31) wsum[wid] = x;
        __syncthreads();
        if (wid == 0) {
            int wv = wsum[lane];
            #pragma unroll
            for (int off = 1; off < 32; off <<= 1) {
                int y = __shfl_up_sync(0xffffffffu, wv, off);
                if (lane >= off) wv += y;
            }
            wsum[lane] = wv;
        }
        __syncthreads();
        int excl = carry + (x - v) + (wid > 0 ? wsum[wid - 1] : 0);
        if (idx < NN) g_rowstart[idx] = excl;   // coalesced
        carry += wsum[31];                      // chunk total (uniform)
        __syncthreads();                        // protect wsum before next chunk
    }
    if (t == 0) g_rowstart[NN] = EE;
}
__global__ void csr_fill_k(const int* __restrict__ src, const int* __restrict__ dst) {
    int e = blockIdx.x * blockDim.x + threadIdx.x;
    if (e >= EE) return;
    int d = dst[e];
    int pos = g_rowstart[d] + atomicAdd(&g_cur[d], 1);
    g_csrc[pos] = src[e];
    g_cdst[pos] = d;
    g_eid[pos]  = e;
}

// ---------------- gather segment-max ----------------
__global__ void gather_max_128(const float* __restrict__ msg, float* __restrict__ agg) {
    int warp = (blockIdx.x * blockDim.x + threadIdx.x) >> 5;
    int lane = threadIdx.x & 31;
    if (warp >= NN) return;
    int rs = g_rowstart[warp], re = g_rowstart[warp + 1];
    float4 v = make_float4(0.f, 0.f, 0.f, 0.f);
    for (int j = rs; j < re; j++) {
        int s = g_csrc[j];
        float4 m = *(const float4*)(msg + (size_t)s * 128 + lane * 4);
        v.x = fmaxf(v.x, m.x); v.y = fmaxf(v.y, m.y);
        v.z = fmaxf(v.z, m.z); v.w = fmaxf(v.w, m.w);
    }
    *(float4*)(agg + (size_t)warp * 128 + lane * 4) = v;
}
__global__ void gather_max_256(const float* __restrict__ msg, float* __restrict__ agg) {
    int warp = (blockIdx.x * blockDim.x + threadIdx.x) >> 5;
    int lane = threadIdx.x & 31;
    if (warp >= NN) return;
    int rs = g_rowstart[warp], re = g_rowstart[warp + 1];
    float4 v0 = make_float4(0.f, 0.f, 0.f, 0.f);
    float4 v1 = v0;
    for (int j = rs; j < re; j++) {
        int s = g_csrc[j];
        const float* row = msg + (size_t)s * 256;
        float4 a = *(const float4*)(row + lane * 4);
        float4 b = *(const float4*)(row + 128 + lane * 4);
        v0.x = fmaxf(v0.x, a.x); v0.y = fmaxf(v0.y, a.y);
        v0.z = fmaxf(v0.z, a.z); v0.w = fmaxf(v0.w, a.w);
        v1.x = fmaxf(v1.x, b.x); v1.y = fmaxf(v1.y, b.y);
        v1.z = fmaxf(v1.z, b.z); v1.w = fmaxf(v1.w, b.w);
    }
    *(float4*)(agg + (size_t)warp * 256 + lane * 4) = v0;
    *(float4*)(agg + (size_t)warp * 256 + 128 + lane * 4) = v1;
}

// ---------------- tf32 GEMM: persistent + 2-stage (R9/R13-proven, FROZEN) ----------
__device__ __forceinline__ unsigned f2tf32(float v) {
    unsigned r;
    asm("cvt.rna.tf32.f32 %0, %1;" : "=r"(r) : "f"(v));
    return r;
}
__device__ __forceinline__ void mma_tf32(float& c0, float& c1, float& c2, float& c3,
                                         unsigned a0, unsigned a1, unsigned a2, unsigned a3,
                                         unsigned b0, unsigned b1) {
    asm volatile("mma.sync.aligned.m16n8k8.row.col.f32.tf32.tf32.f32 "
                 "{%0,%1,%2,%3}, {%4,%5,%6,%7}, {%8,%9}, {%0,%1,%2,%3};"
                 : "+f"(c0), "+f"(c1), "+f"(c2), "+f"(c3)
                 : "r"(a0), "r"(a1), "r"(a2), "r"(a3), "r"(b0), "r"(b1));
}

#define AS_STRIDE 36
#define BS_STRIDE 136
#define AS_ELEMS (128 * AS_STRIDE)
#define BS_ELEMS (32 * BS_STRIDE)
#define TG_SMEM ((2 * AS_ELEMS + 2 * BS_ELEMS) * 4)

template<bool HAS2, bool BIAS, bool RELU, bool DUAL>
__global__ __launch_bounds__(256, 2) void tgemm(
        const float* __restrict__ A, const float* __restrict__ W,
        const float* __restrict__ A2, const float* __restrict__ W2,
        const float* __restrict__ bias, float* __restrict__ out,
        const float* __restrict__ Wb, float* __restrict__ outb,
        const float* __restrict__ cls5, const float* __restrict__ Wp5,
        const float* __restrict__ Wq5, const float* __restrict__ b1f,
        int M, int K, int N) {
    extern __shared__ unsigned sm[];
    unsigned* AsBase = sm;
    unsigned* BsBase = sm + 2 * AS_ELEMS;
    int t = threadIdx.x;
    int w = t >> 5, lane = t & 31;
    int g = lane >> 2, q = lane & 3;
    int wm = (w >> 2) * 64, wn = (w & 3) * 32;
    int a_row = t >> 3, a_k = (t & 7) * 4;
    int w_k = t >> 5, w_n = (t & 31) * 4;

    int mtiles = (M + 127) >> 7;
    int ntiles = N >> 7;
    int tot = mtiles * ntiles;
    int tot_all = DUAL ? tot * 2 : tot;
    int kslabs = K >> 5;
    int nslab = (HAS2 ? 2 : 1) * kslabs;

    for (int tt = blockIdx.x; tt < tot_all; tt += gridDim.x) {
        bool second = DUAL && (tt >= tot);
        int tile = second ? tt - tot : tt;
        const float* Wsel = second ? Wb : W;
        float* outsel = second ? outb : out;
        int bm = (tile / ntiles) * 128, bn = (tile % ntiles) * 128;

        float acc[4][4][4];
        #pragma unroll
        for (int i = 0; i < 4; i++)
            #pragma unroll
            for (int j = 0; j < 4; j++)
                #pragma unroll
                for (int r = 0; r < 4; r++) acc[i][j][r] = 0.f;

        float4 aP[4], wP[4];
        auto ldA = [&](int j) {
            const float* Ap = (HAS2 && j >= kslabs) ? A2 : A;
            int k0 = (j & (kslabs - 1)) << 5;
            #pragma unroll
            for (int ph = 0; ph < 4; ph++) {
                int grow = bm + a_row + ph * 32;
                aP[ph] = make_float4(0.f, 0.f, 0.f, 0.f);
                if (grow < M) aP[ph] = *(const float4*)(Ap + (size_t)grow * K + k0 + a_k);
            }
        };
        auto ldB = [&](int j) {
            const float* Wp = (HAS2 && j >= kslabs) ? W2 : Wsel;
            int k0 = (j & (kslabs - 1)) << 5;
            #pragma unroll
            for (int ph = 0; ph < 4; ph++)
                wP[ph] = *(const float4*)(Wp + (size_t)(k0 + w_k + ph * 8) * N + bn + w_n);
        };
        auto stStage = [&](int st) {
            unsigned* As = AsBase + st * AS_ELEMS;
            unsigned* Bs = BsBase + st * BS_ELEMS;
            #pragma unroll
            for (int ph = 0; ph < 4; ph++) {
                unsigned* p = &As[(a_row + ph * 32) * AS_STRIDE + a_k];
                p[0] = f2tf32(aP[ph].x); p[1] = f2tf32(aP[ph].y);
                p[2] = f2tf32(aP[ph].z); p[3] = f2tf32(aP[ph].w);
                unsigned* pw = &Bs[(w_k + ph * 8) * BS_STRIDE + w_n];
                pw[0] = f2tf32(wP[ph].x); pw[1] = f2tf32(wP[ph].y);
                pw[2] = f2tf32(wP[ph].z); pw[3] = f2tf32(wP[ph].w);
            }
        };

        ldA(0); ldB(0);
        stStage(0);
        __syncthreads();
        if (nslab > 1) ldA(1);

        for (int j = 0; j < nslab; j++) {
            int s = j & 1;
            const unsigned* As = AsBase + s * AS_ELEMS;
            const unsigned* Bs = BsBase + s * BS_ELEMS;
            #pragma unroll
            for (int kk = 0; kk < 32; kk += 8) {
                unsigned af[4][4], bf[4][2];
                #pragma unroll
                for (int mi = 0; mi < 4; mi++) {
                    const unsigned* p = &As[(wm + mi * 16 + g) * AS_STRIDE + kk + q];
                    af[mi][0] = p[0];
                    af[mi][1] = p[8 * AS_STRIDE];
                    af[mi][2] = p[4];
                    af[mi][3] = p[8 * AS_STRIDE + 4];
                }
                #pragma unroll
                for (int ni = 0; ni < 4; ni++) {
                    const unsigned* p = &Bs[(kk + q) * BS_STRIDE + wn + ni * 8 + g];
                    bf[ni][0] = p[0];
                    bf[ni][1] = p[4 * BS_STRIDE];
                }
                #pragma unroll
                for (int mi = 0; mi < 4; mi++)
                    #pragma unroll
                    for (int ni = 0; ni < 4; ni++)
                        mma_tf32(acc[mi][ni][0], acc[mi][ni][1], acc[mi][ni][2], acc[mi][ni][3],
                                 af[mi][0], af[mi][1], af[mi][2], af[mi][3],
                                 bf[ni][0], bf[ni][1]);
            }
            if (j + 1 < nslab) {
                ldB(j + 1);
                stStage(1 - s);
                if (j + 2 < nslab) ldA(j + 2);
            }
            __syncthreads();
        }

        // DUAL: stage rank-5 fold weights (+ b1 for Q) into now-free smem
        float* fw = (float*)sm;         // [5][128]
        float* fb = fw + 5 * 128;       // [128]
        if (DUAL) {
            const float* Wf = second ? Wq5 : Wp5;
            for (int i = t; i < 5 * 128; i += 256) {
                int r = i >> 7, c = i & 127;
                fw[i] = Wf[r * 256 + bn + c];
            }
            if (second) for (int i = t; i < 128; i += 256) fb[i] = b1f[bn + i];
            __syncthreads();
        }

        #pragma unroll
        for (int mi = 0; mi < 4; mi++) {
            int r0 = bm + wm + mi * 16 + g;
            float cA[5], cB[5];
            if (DUAL) {
                #pragma unroll
                for (int i = 0; i < 5; i++) {
                    cA[i] = (r0 < M) ? cls5[(size_t)r0 * 5 + i] : 0.f;
                    cB[i] = (r0 + 8 < M) ? cls5[(size_t)(r0 + 8) * 5 + i] : 0.f;
                }
            }
            #pragma unroll
            for (int ni = 0; ni < 4; ni++) {
                int colL = wn + ni * 8 + q * 2;
                int col = bn + colL;
                float b0 = 0.f, b1v = 0.f;
                if (BIAS) { b0 = bias[col]; b1v = bias[col + 1]; }
                float2 lo, hi;
                lo.x = acc[mi][ni][0] + b0; lo.y = acc[mi][ni][1] + b1v;
                hi.x = acc[mi][ni][2] + b0; hi.y = acc[mi][ni][3] + b1v;
                if (DUAL) {
                    float d0a = 0.f, d1a = 0.f, d0b = 0.f, d1b = 0.f;
                    #pragma unroll
                    for (int i = 0; i < 5; i++) {
                        float w0 = fw[i * 128 + colL], w1 = fw[i * 128 + colL + 1];
                        d0a += cA[i] * w0; d1a += cA[i] * w1;
                        d0b += cB[i] * w0; d1b += cB[i] * w1;
                    }
                    lo.x += d0a; lo.y += d1a;
                    hi.x += d0b; hi.y += d1b;
                    if (second) {
                        float fb0 = fb[colL], fb1 = fb[colL + 1];
                        lo.x += fb0; lo.y += fb1;
                        hi.x += fb0; hi.y += fb1;
                    }
                }
                if (RELU) {
                    lo.x = fmaxf(lo.x, 0.f); lo.y = fmaxf(lo.y, 0.f);
                    hi.x = fmaxf(hi.x, 0.f); hi.y = fmaxf(hi.y, 0.f);
                }
                if (r0 < M)     *(float2*)(outsel + (size_t)r0 * N + col) = lo;
                if (r0 + 8 < M) *(float2*)(outsel + (size_t)(r0 + 8) * N + col) = hi;
            }
        }
        if (DUAL) __syncthreads();
    }
}

// ---------------- node head ----------------
__global__ void node_head_k(const float* __restrict__ h1, const float* __restrict__ npW,
                            const float* __restrict__ npb, const float* __restrict__ g,
                            const float* __restrict__ beta, float* __restrict__ node_pred,
                            float* __restrict__ cls) {
    int warp = (blockIdx.x * blockDim.x + threadIdx.x) >> 5;
    int lane = threadIdx.x & 31;
    if (warp >= NN) return;
    const float* row = h1 + (size_t)warp * D_HID;
    float p[5] = {};
    for (int k = lane; k < D_HID; k += 32) {
        float hv = row[k];
        #pragma unroll
        for (int j = 0; j < 5; j++) p[j] += hv * npW[k * 5 + j];
    }
    #pragma unroll
    for (int off = 16; off; off >>= 1)
        #pragma unroll
        for (int j = 0; j < 5; j++) p[j] += __shfl_xor_sync(0xffffffffu, p[j], off);
    #pragma unroll
    for (int j = 0; j < 5; j++) p[j] += npb[j];
    float mu = (p[0] + p[1] + p[2] + p[3] + p[4]) * 0.2f;
    float var = 0.f;
    #pragma unroll
    for (int j = 0; j < 5; j++) { float t = p[j] - mu; var += t * t; }
    var *= 0.2f;
    float inv = rsqrtf(var + EPS);
    float y[5];
    #pragma unroll
    for (int j = 0; j < 5; j++) y[j] = g[j] * (p[j] - mu) * inv + beta[j];
    float mx = y[0];
    #pragma unroll
    for (int j = 1; j < 5; j++) mx = fmaxf(mx, y[j]);
    float es[5], se = 0.f;
    #pragma unroll
    for (int j = 0; j < 5; j++) { es[j] = __expf(y[j] - mx); se += es[j]; }
    float rse = 1.f / se;
    if (lane == 0) {
        #pragma unroll
        for (int j = 0; j < 5; j++) {
            node_pred[(size_t)warp * 5 + j] = y[j];
            cls[(size_t)warp * 5 + j] = es[j] * rse;
        }
    }
}

// ---------------- edge head: reg weights + cached Q row (CSR dst-grouped) ----------
#define EH_EPW 16
__global__ __launch_bounds__(256, 2) void edge_head_k(
        const float* __restrict__ P, const float* __restrict__ Q,
        const float* __restrict__ efeat, const float* __restrict__ W1,
        const float* __restrict__ g, const float* __restrict__ beta,
        const float* __restrict__ W2, const float* __restrict__ b2,
        float* __restrict__ out) {
    int gw = (blockIdx.x * blockDim.x + threadIdx.x) >> 5;
    int lane = threadIdx.x & 31;
    int f0 = lane * 8;

    float we[6][8];
    #pragma unroll
    for (int i = 0; i < 6; i++) {
        float4 a = *(const float4*)(W1 + (261 + i) * 256 + f0);
        float4 b = *(const float4*)(W1 + (261 + i) * 256 + f0 + 4);
        we[i][0] = a.x; we[i][1] = a.y; we[i][2] = a.z; we[i][3] = a.w;
        we[i][4] = b.x; we[i][5] = b.y; we[i][6] = b.z; we[i][7] = b.w;
    }
    float w2a[8], w2b[8], gv[8], bv[8];
    #pragma unroll
    for (int i = 0; i < 8; i++) {
        w2a[i] = W2[(f0 + i) * 2 + 0];
        w2b[i] = W2[(f0 + i) * 2 + 1];
        gv[i] = g[f0 + i];
        bv[i] = beta[f0 + i];
    }
    float b20 = b2[0], b21 = b2[1];

    int jbase = gw * EH_EPW;
    int d_prev = -1;
    float qc[8];
    #pragma unroll 1
    for (int ii = 0; ii < EH_EPW; ii++) {
        int j = jbase + ii;
        if (j >= EE) break;
        int s = g_csrc[j], d = g_cdst[j], e = g_eid[j];
        if (d != d_prev) {
            float4 qa = *(const float4*)(Q + (size_t)d * 256 + f0);
            float4 qb = *(const float4*)(Q + (size_t)d * 256 + f0 + 4);
            qc[0] = qa.x; qc[1] = qa.y; qc[2] = qa.z; qc[3] = qa.w;
            qc[4] = qb.x; qc[5] = qb.y; qc[6] = qb.z; qc[7] = qb.w;
            d_prev = d;
        }
        float y[8];
        {
            float4 pa = *(const float4*)(P + (size_t)s * 256 + f0);
            float4 pb = *(const float4*)(P + (size_t)s * 256 + f0 + 4);
            y[0] = pa.x + qc[0]; y[1] = pa.y + qc[1]; y[2] = pa.z + qc[2]; y[3] = pa.w + qc[3];
            y[4] = pb.x + qc[4]; y[5] = pb.y + qc[5]; y[6] = pb.z + qc[6]; y[7] = pb.w + qc[7];
        }
        float ev = 0.f;
        if (lane < 6) ev = efeat[(size_t)e * 6 + lane];
        #pragma unroll
        for (int i = 0; i < 6; i++) {
            float ci = __shfl_sync(0xffffffffu, ev, i);
            #pragma unroll
            for (int r = 0; r < 8; r++) y[r] += ci * we[i][r];
        }
        float sum = 0.f;
        #pragma unroll
        for (int i = 0; i < 8; i++) sum += y[i];
        #pragma unroll
        for (int off = 16; off; off >>= 1) sum += __shfl_xor_sync(0xffffffffu, sum, off);
        float mu = sum * (1.f / 256.f);
        float vs = 0.f;
        #pragma unroll
        for (int i = 0; i < 8; i++) { float t = y[i] - mu; vs += t * t; }
        #pragma unroll
        for (int off = 16; off; off >>= 1) vs += __shfl_xor_sync(0xffffffffu, vs, off);
        float inv = rsqrtf(vs * (1.f / 256.f) + EPS);
        float o0 = 0.f, o1 = 0.f;
        #pragma unroll
        for (int i = 0; i < 8; i++) {
            float yn = gv[i] * (y[i] - mu) * inv + bv[i];
            yn = fmaxf(yn, 0.f);
            o0 += yn * w2a[i];
            o1 += yn * w2b[i];
        }
        #pragma unroll
        for (int off = 16; off; off >>= 1) {
            o0 += __shfl_xor_sync(0xffffffffu, o0, off);
            o1 += __shfl_xor_sync(0xffffffffu, o1, off);
        }
        if (lane == 0) {
            out[(size_t)e * 2 + 0] = o0 + b20;
            out[(size_t)e * 2 + 1] = o1 + b21;
        }
    }
}

// ---------------- launch ----------------
static inline int ggrid(int tiles) {
    int passes = (tiles + 295) / 296;
    return (tiles + passes - 1) / passes;
}

extern "C" void kernel_launch(void* const* d_in, const int* in_sizes, int n_in,
                              void* d_out, int out_size) {
    const float* h        = (const float*)d_in[0];
    const float* efeat    = (const float*)d_in[1];
    const int*   src      = (const int*)  d_in[2];
    const int*   dst      = (const int*)  d_in[3];
    const float* encWpool = (const float*)d_in[4];
    const float* encbpool = (const float*)d_in[5];
    const float* encWself = (const float*)d_in[6];
    const float* encbself = (const float*)d_in[7];
    const float* encWneigh= (const float*)d_in[8];
    const float* npW      = (const float*)d_in[9];
    const float* npb      = (const float*)d_in[10];
    const float* npg      = (const float*)d_in[11];
    const float* npbeta   = (const float*)d_in[12];
    const float* epW1     = (const float*)d_in[13];
    const float* epb1     = (const float*)d_in[14];
    const float* epg      = (const float*)d_in[15];
    const float* epbeta   = (const float*)d_in[16];
    const float* epW2     = (const float*)d_in[17];
    const float* epb2     = (const float*)d_in[18];
    const float* decWpool = (const float*)d_in[19];
    const float* decbpool = (const float*)d_in[20];
    const float* decWself = (const float*)d_in[21];
    const float* decbself = (const float*)d_in[22];
    const float* decWneigh= (const float*)d_in[23];

    float* out       = (float*)d_out;
    float* node_pred = out;
    float* edge_pred = out + NN * 5;
    float* h2        = out + NN * 5 + EE * 2;

    float *m1, *agg1, *h1, *cls, *P, *Q, *m2, *agg2;
    cudaGetSymbolAddress((void**)&m1,  g_m1);
    cudaGetSymbolAddress((void**)&agg1,g_agg1);
    cudaGetSymbolAddress((void**)&h1,  g_h1);
    cudaGetSymbolAddress((void**)&cls, g_cls);
    cudaGetSymbolAddress((void**)&P,   g_P);
    cudaGetSymbolAddress((void**)&Q,   g_Q);
    cudaGetSymbolAddress((void**)&m2,  g_m2);
    cudaGetSymbolAddress((void**)&agg2,g_agg2);

    static cudaStream_t s2 = nullptr;
    static cudaEvent_t evFork1 = nullptr, evJoin1 = nullptr, evFork2 = nullptr,
                       evJoin2 = nullptr;
    if (s2 == nullptr) {
        cudaStreamCreateWithFlags(&s2, cudaStreamNonBlocking);
        cudaEventCreateWithFlags(&evFork1, cudaEventDisableTiming);
        cudaEventCreateWithFlags(&evJoin1, cudaEventDisableTiming);
        cudaEventCreateWithFlags(&evFork2, cudaEventDisableTiming);
        cudaEventCreateWithFlags(&evJoin2, cudaEventDisableTiming);
        cudaFuncSetAttribute(tgemm<false, true,  true,  false>, cudaFuncAttributeMaxDynamicSharedMemorySize, TG_SMEM);
        cudaFuncSetAttribute(tgemm<true,  true,  true,  false>, cudaFuncAttributeMaxDynamicSharedMemorySize, TG_SMEM);
        cudaFuncSetAttribute(tgemm<false, false, false, true >, cudaFuncAttributeMaxDynamicSharedMemorySize, TG_SMEM);
    }

    // fork 1: the ENTIRE CSR chain runs on s2, overlapped with the enc-pool GEMM
    cudaEventRecord(evFork1, 0);
    cudaStreamWaitEvent(s2, evFork1, 0);

    // main: encoder pool GEMM (needs only h)
    tgemm<false, true, true, false><<<ggrid(235), 256, TG_SMEM>>>(
        h, encWpool, nullptr, nullptr, encbpool, m1, nullptr, nullptr,
        nullptr, nullptr, nullptr, nullptr, NN, D_IN, D_IN);

    // s2: CSR build (zero -> hist -> scan -> fill)
    csr_zero_k<<<(NN + 255) / 256, 256, 0, s2>>>();
    csr_hist_k<<<(EE + 255) / 256, 256, 0, s2>>>(dst);
    csr_scan_k<<<1, 1024, 0, s2>>>();
    csr_fill_k<<<(EE + 255) / 256, 256, 0, s2>>>(src, dst);
    cudaEventRecord(evJoin1, s2);
    cudaStreamWaitEvent(0, evJoin1, 0);

    gather_max_128<<<(NN * 32 + 255) / 256, 256>>>(m1, agg1);

    tgemm<true, true, true, false><<<ggrid(470), 256, TG_SMEM>>>(
        h, encWself, agg1, encWneigh, encbself, h1, nullptr, nullptr,
        nullptr, nullptr, nullptr, nullptr, NN, D_IN, D_HID);

    // node head on main (cls must precede the fused P/Q GEMM)
    node_head_k<<<(NN * 32 + 255) / 256, 256>>>(h1, npW, npb, npg, npbeta, node_pred, cls);

    // fork 2: decoder branch on s2, edge branch on main (full grids)
    cudaEventRecord(evFork2, 0);
    cudaStreamWaitEvent(s2, evFork2, 0);

    tgemm<false, true, true, false><<<ggrid(470), 256, TG_SMEM, s2>>>(
        h1, decWpool, nullptr, nullptr, decbpool, m2, nullptr, nullptr,
        nullptr, nullptr, nullptr, nullptr, NN, D_HID, D_HID);
    gather_max_256<<<(NN * 32 + 255) / 256, 256, 0, s2>>>(m2, agg2);
    tgemm<true, true, true, false><<<ggrid(235), 256, TG_SMEM, s2>>>(
        h1, decWself, agg2, decWneigh, decbself, h2, nullptr, nullptr,
        nullptr, nullptr, nullptr, nullptr, NN, D_HID, D_IN);
    cudaEventRecord(evJoin2, s2);

    // edge branch (main): fused P/Q GEMM (fold inlined) -> edge head
    tgemm<false, false, false, true><<<ggrid(940), 256, TG_SMEM>>>(
        h1, epW1, nullptr, nullptr, nullptr, P, epW1 + 267 * 256, Q,
        cls, epW1 + 256 * 256, epW1 + 523 * 256, epb1, NN, D_HID, D_HID);
    edge_head_k<<<(EE + EH_EPW * 8 - 1) / (EH_EPW * 8), 256>>>(
        P, Q, efeat, epW1, epg, epbeta, epW2, epb2, edge_pred);

    // join decoder branch back into main
    cudaStreamWaitEvent(0, evJoin2, 0);
}